// round 6
// baseline (speedup 1.0000x reference)
#include <cuda_runtime.h>
#include <cstdint>

#define BN   128
#define LN   256
#define HN   256
#define ENM  30
#define TT   501
#define H3   768

// ---- static device scratch (no allocation) ----
__device__ __align__(16) float g_WcombT[256 * 1024];            // [j][o] o<256: W_h2h col, else W_hh
__device__ __align__(16) float g_WihcT[512 * H3];               // [c][k]
__device__ __align__(16) float g_Wcat1[512 * 256];              // [c][n] for proj GEMM
__device__ __align__(16) float g_projT[(size_t)BN * HN * LN];   // [b][h][l]
__device__ __align__(16) float g_P[BN * LN * 4];
__device__ __align__(16) float g_WgenT[HN * 32];
__device__ __align__(16) float g_WlgHT[HN * 4];
__device__ __align__(16) float g_OH[ENM * H3];
__device__ float g_S[4];
__device__ float g_hid4[(size_t)BN * TT * 4];

__device__ __forceinline__ float tanhfast(float x) {
    // tanh(x) = sign(x) * (1 - 2/(exp(2|x|)+1)); ex2/rcp approx ~1e-6 abs err
    float e, r;
    asm("ex2.approx.f32 %0, %1;" : "=f"(e) : "f"(fabsf(x) * 2.8853900817779268f));
    asm("rcp.approx.f32 %0, %1;" : "=f"(r) : "f"(e + 1.0f));
    return copysignf(1.0f - 2.0f * r, x);
}
__device__ __forceinline__ float sigm(float x) { return 1.0f / (1.0f + __expf(-x)); }

// ---- K0: pack weights ----
__global__ void k0_prep(const float* __restrict__ W_i2h, const float* __restrict__ W_h2h,
                        const float* __restrict__ W_ih,  const float* __restrict__ W_hh,
                        const float* __restrict__ W_gen, const float* __restrict__ W_lg)
{
    const int O1 = 256 * 1024;           // WcombT
    const int O2 = O1 + 512 * 768;       // WihcT
    const int O3 = O2 + 512 * 256;       // Wcat1
    const int O4 = O3 + 256 * 32;        // WgenT
    const int O5 = O4 + 256 * 4;         // WlgHT
    const int O6 = O5 + 30 * 768;        // OH
    const int TOT = O6 + 4;
    for (int i = blockIdx.x * blockDim.x + threadIdx.x; i < TOT; i += gridDim.x * blockDim.x) {
        if (i < O1) {
            int j = i >> 10, o = i & 1023;
            g_WcombT[i] = (o < 256) ? W_h2h[o * 256 + j] : W_hh[(o - 256) * 256 + j];
        } else if (i < O2) {
            int e = i - O1, c = e / 768, k = e % 768;
            g_WihcT[e] = W_ih[k * 542 + c];
        } else if (i < O3) {
            int e = i - O2, c = e >> 8, n = e & 255;
            g_Wcat1[e] = W_i2h[n * 512 + c];
        } else if (i < O4) {
            int e = i - O3, j = e >> 5, m = e & 31;
            g_WgenT[e] = (m < 30) ? W_gen[m * 256 + j] : 0.0f;
        } else if (i < O5) {
            int e = i - O4, j = e >> 2, m = e & 3;
            g_WlgHT[e] = W_lg[m * 768 + j];
        } else if (i < O6) {
            int e = i - O5, eo = e / 768, k = e % 768;
            g_OH[e] = W_ih[k * 542 + 512 + eo];
        } else {
            int j = i - O6; float s = 0.0f;
            for (int c = 0; c < 512; c++) s += W_lg[j * 768 + 256 + c];
            g_S[j] = s;
        }
    }
}

// ---- KP: P[b,l,j] = fea[b,l,:]·W_lg[j,256:768] ----
__global__ __launch_bounds__(256) void kP(const float* __restrict__ fea, const float* __restrict__ W_lg)
{
    __shared__ float Wl[4 * 512];
    const int b = blockIdx.y, tid = threadIdx.x, lane = tid & 31, w = tid >> 5;
    for (int i = tid; i < 2048; i += 256) Wl[i] = W_lg[(i >> 9) * 768 + 256 + (i & 511)];
    __syncthreads();
    int l = blockIdx.x * 8 + w;
    float a0 = 0, a1 = 0, a2 = 0, a3 = 0;
    const float* fp = fea + ((size_t)(b * 256 + l)) * 512;
    for (int i = 0; i < 16; i++) {
        int c = lane + 32 * i; float f = fp[c];
        a0 = fmaf(f, Wl[c], a0); a1 = fmaf(f, Wl[512 + c], a1);
        a2 = fmaf(f, Wl[1024 + c], a2); a3 = fmaf(f, Wl[1536 + c], a3);
    }
    for (int o = 16; o; o >>= 1) {
        a0 += __shfl_xor_sync(~0u, a0, o); a1 += __shfl_xor_sync(~0u, a1, o);
        a2 += __shfl_xor_sync(~0u, a2, o); a3 += __shfl_xor_sync(~0u, a3, o);
    }
    if (lane < 4) {
        float v = (lane == 0) ? a0 : (lane == 1) ? a1 : (lane == 2) ? a2 : a3;
        g_P[(size_t)(b * 256 + l) * 4 + lane] = v;
    }
}

// ---- K1: [32768 x 512] @ [512 x 256] -> projT (transposed store) ----
__global__ __launch_bounds__(256) void k1_gemm(const float* __restrict__ fea)
{
    __shared__ float As[16 * 128];
    __shared__ float Bs[16 * 128];
    const int m0 = blockIdx.y * 128, n0 = blockIdx.x * 128;
    const int tid = threadIdx.x, ty = tid >> 4, tx = tid & 15;
    float acc[8][8];
#pragma unroll
    for (int i = 0; i < 8; i++)
#pragma unroll
        for (int j = 0; j < 8; j++) acc[i][j] = 0.0f;

    for (int k0 = 0; k0 < 512; k0 += 16) {
#pragma unroll
        for (int s = 0; s < 2; s++) {
            int idx = tid + s * 256;
            int row = idx >> 2, c4 = idx & 3;
            float4 v = *(const float4*)(fea + (size_t)(m0 + row) * 512 + k0 + c4 * 4);
            As[(c4 * 4 + 0) * 128 + row] = v.x; As[(c4 * 4 + 1) * 128 + row] = v.y;
            As[(c4 * 4 + 2) * 128 + row] = v.z; As[(c4 * 4 + 3) * 128 + row] = v.w;
        }
#pragma unroll
        for (int s = 0; s < 2; s++) {
            int idx = tid + s * 256;
            int kk = idx >> 5, n4 = idx & 31;
            *(float4*)(Bs + kk * 128 + n4 * 4) =
                *(const float4*)(g_Wcat1 + (size_t)(k0 + kk) * 256 + n0 + n4 * 4);
        }
        __syncthreads();
#pragma unroll
        for (int kk = 0; kk < 16; kk++) {
            float4 a0 = *(float4*)(As + kk * 128 + ty * 8);
            float4 a1 = *(float4*)(As + kk * 128 + ty * 8 + 4);
            float4 b0 = *(float4*)(Bs + kk * 128 + tx * 8);
            float4 b1 = *(float4*)(Bs + kk * 128 + tx * 8 + 4);
            float av[8] = {a0.x, a0.y, a0.z, a0.w, a1.x, a1.y, a1.z, a1.w};
            float bv[8] = {b0.x, b0.y, b0.z, b0.w, b1.x, b1.y, b1.z, b1.w};
#pragma unroll
            for (int i = 0; i < 8; i++)
#pragma unroll
                for (int j = 0; j < 8; j++) acc[i][j] = fmaf(av[i], bv[j], acc[i][j]);
        }
        __syncthreads();
    }
    const int b = m0 >> 8, l0 = m0 & 255;
#pragma unroll
    for (int i = 0; i < 8; i++)
#pragma unroll
        for (int j = 0; j < 8; j++)
            g_projT[((size_t)b * 256 + n0 + tx * 8 + j) * 256 + l0 + ty * 8 + i] = acc[i][j];
}

// ---- K2: 501-step recurrence, 2 batch rows per CTA ----
__global__ __launch_bounds__(1024, 1) void k2_loop(
    const float* __restrict__ fea,
    const float* __restrict__ b_h2h, const float* __restrict__ b_ih,
    const float* __restrict__ b_hh,  const float* __restrict__ w_score,
    const float* __restrict__ b_gen, float* __restrict__ probs_out)
{
    const int b0 = blockIdx.x * 2, tid = threadIdx.x;
    __shared__ __align__(16) float2 h2[256];                 // interleaved rows
    __shared__ __align__(16) float q_s[512], gh_s[1536], gi_s[1536];
    __shared__ __align__(16) float e_s[512], ctx_s[1024];
    __shared__ __align__(16) float scr[2048];
    __shared__ float ws_s[256], bh2h_s[256], bih_s[768], bhh_s[768], bgen_s[32];
    __shared__ int elem_sh[2];

    if (tid < 256) { h2[tid] = make_float2(0.f, 0.f); ws_s[tid] = w_score[tid]; bh2h_s[tid] = b_h2h[tid]; }
    if (tid < 768) { bih_s[tid] = b_ih[tid]; bhh_s[tid] = b_hh[tid]; }
    if (tid < 32)  bgen_s[tid] = (tid < 30) ? b_gen[tid] : 0.0f;
    if (tid < 2)   elem_sh[tid] = 0;
    __syncthreads();

    const float* proj0 = g_projT + (size_t)b0 * 65536;

    for (int t = 0; t < TT; t++) {
        // ---- A: [q|gh] = Wcomb @ h for both rows; split-j halves, float2 over outputs
        {
            const int hf = tid >> 9, p = tid & 511, o0 = 2 * p;
            const float* w = g_WcombT + (size_t)(hf * 128) * 1024 + o0;
            float a00 = 0, a10 = 0, a01 = 0, a11 = 0;
#pragma unroll 8
            for (int j = 0; j < 128; j++) {
                float2 wv = *(const float2*)(w + j * 1024);
                float2 hh = h2[hf * 128 + j];
                a00 = fmaf(wv.x, hh.x, a00); a10 = fmaf(wv.x, hh.y, a10);
                a01 = fmaf(wv.y, hh.x, a01); a11 = fmaf(wv.y, hh.y, a11);
            }
            if (hf) *(float4*)(scr + 4 * p) = make_float4(a00, a10, a01, a11);
            __syncthreads();
            if (!hf) {
                float4 f = *(float4*)(scr + 4 * p);
                a00 += f.x; a10 += f.y; a01 += f.z; a11 += f.w;
                if (o0 < 256) {
                    q_s[o0] = a00 + bh2h_s[o0];         q_s[256 + o0] = a10 + bh2h_s[o0];
                    q_s[o0 + 1] = a01 + bh2h_s[o0 + 1]; q_s[256 + o0 + 1] = a11 + bh2h_s[o0 + 1];
                } else {
                    int k = o0 - 256;
                    gh_s[k] = a00 + bhh_s[k];           gh_s[768 + k] = a10 + bhh_s[k];
                    gh_s[k + 1] = a01 + bhh_s[k + 1];   gh_s[768 + k + 1] = a11 + bhh_s[k + 1];
                }
            }
            __syncthreads();
        }
        // ---- B: e[r][l] = sum_h ws[h]*tanh(proj[r][h][l]+q[r][h]); (r, l-pair, h-quarter)
        {
            const int r = tid >> 9, rem = tid & 511, lp = rem & 127, c4 = rem >> 7;
            const float* pb = proj0 + (size_t)r * 65536 + (size_t)(c4 * 64) * 256 + 2 * lp;
            const float* qr = q_s + r * 256 + c4 * 64;
            const float* wr = ws_s + c4 * 64;
            float p0 = 0, p1 = 0;
#pragma unroll 8
            for (int hh = 0; hh < 64; hh++) {
                float2 pr = *(const float2*)(pb + hh * 256);
                float qv = qr[hh], wv = wr[hh];
                p0 = fmaf(wv, tanhfast(pr.x + qv), p0);
                p1 = fmaf(wv, tanhfast(pr.y + qv), p1);
            }
            *(float2*)(scr + 2 * tid) = make_float2(p0, p1);
        }
        __syncthreads();
        if (tid < 512) {
            const int r = tid >> 8, l = tid & 255, lp = l >> 1, sub = l & 1;
            float e = 0;
#pragma unroll
            for (int c4 = 0; c4 < 4; c4++) {
                float2 v = *(const float2*)(scr + 2 * (r * 512 + c4 * 128 + lp));
                e += sub ? v.y : v.x;
            }
            e_s[tid] = e;
        }
        __syncthreads();
        // ---- softmax per row (warps 0-7 row0, 8-15 row1)
        if (tid < 512) {
            float v = e_s[tid];
            for (int o = 16; o; o >>= 1) v = fmaxf(v, __shfl_xor_sync(~0u, v, o));
            if ((tid & 31) == 0) scr[1920 + (tid >> 5)] = v;
        }
        __syncthreads();
        if (tid < 512) {
            const int r = tid >> 8;
            float mx = scr[1920 + r * 8];
#pragma unroll
            for (int w = 1; w < 8; w++) mx = fmaxf(mx, scr[1920 + r * 8 + w]);
            float a = __expf(e_s[tid] - mx);
            e_s[tid] = a;
            for (int o = 16; o; o >>= 1) a += __shfl_xor_sync(~0u, a, o);
            if ((tid & 31) == 0) scr[1952 + (tid >> 5)] = a;
        }
        __syncthreads();
        if (tid < 512) {
            const int r = tid >> 8;
            float s = scr[1952 + r * 8];
#pragma unroll
            for (int w = 1; w < 8; w++) s += scr[1952 + r * 8 + w];
            e_s[tid] *= (1.0f / s);
        }
        __syncthreads();
        // ---- ctx[r][c] = sum_l alpha[r][l]*fea[r][l][c]; (r, c-pair, l-half)
        {
            const int r = tid >> 9, rem = tid & 511, cp = rem & 255, lh = rem >> 8;
            const float* fp = fea + ((size_t)(b0 + r) * 256 + lh * 128) * 512 + 2 * cp;
            const float* al = e_s + r * 256 + lh * 128;
            float a0 = 0, a1 = 0;
#pragma unroll 8
            for (int l = 0; l < 128; l++) {
                float2 fv = *(const float2*)(fp + (size_t)l * 512);
                float av = al[l];
                a0 = fmaf(av, fv.x, a0); a1 = fmaf(av, fv.y, a1);
            }
            if (lh) *(float2*)(scr + 2 * (r * 256 + cp)) = make_float2(a0, a1);
            __syncthreads();
            if (!lh) {
                float2 f = *(float2*)(scr + 2 * (r * 256 + cp));
                ctx_s[r * 512 + 2 * cp] = a0 + f.x;
                ctx_s[r * 512 + 2 * cp + 1] = a1 + f.y;
            }
            __syncthreads();
        }
        // ---- C: gi[r][k] = W_ihc @ ctx[r] + b_ih + OH[elem_r]; (k-pair, c-half)
        {
            const bool act = tid < 768;
            const int snd = (tid >= 384 && tid < 768) ? 1 : 0;
            const int p = act ? (tid - snd * 384) : 0, k0 = 2 * p;
            float a00 = 0, a10 = 0, a01 = 0, a11 = 0;
            if (act) {
                const float* w = g_WihcT + (size_t)(snd * 256) * 768 + k0;
                const float* c0p = ctx_s + snd * 256;
                const float* c1p = ctx_s + 512 + snd * 256;
#pragma unroll 8
                for (int c = 0; c < 256; c++) {
                    float2 wv = *(const float2*)(w + (size_t)c * 768);
                    float cv0 = c0p[c], cv1 = c1p[c];
                    a00 = fmaf(wv.x, cv0, a00); a10 = fmaf(wv.x, cv1, a10);
                    a01 = fmaf(wv.y, cv0, a01); a11 = fmaf(wv.y, cv1, a11);
                }
                if (snd) *(float4*)(scr + 4 * p) = make_float4(a00, a10, a01, a11);
            }
            __syncthreads();
            if (act && !snd) {
                float4 f = *(float4*)(scr + 4 * p);
                const int e0 = elem_sh[0], e1 = elem_sh[1];
                gi_s[k0]           = a00 + f.x + bih_s[k0]     + g_OH[e0 * 768 + k0];
                gi_s[768 + k0]     = a10 + f.y + bih_s[k0]     + g_OH[e1 * 768 + k0];
                gi_s[k0 + 1]       = a01 + f.z + bih_s[k0 + 1] + g_OH[e0 * 768 + k0 + 1];
                gi_s[768 + k0 + 1] = a11 + f.w + bih_s[k0 + 1] + g_OH[e1 * 768 + k0 + 1];
            }
            __syncthreads();
        }
        // ---- D: GRU combine
        if (tid < 512) {
            const int r = tid >> 8, i = tid & 255;
            const float* gir = gi_s + r * 768;
            const float* ghr = gh_s + r * 768;
            float rg = sigm(gir[i] + ghr[i]);
            float z  = sigm(gir[256 + i] + ghr[256 + i]);
            float n  = tanhfast(gir[512 + i] + rg * ghr[512 + i]);
            float* hp = (float*)h2;
            float hprev = hp[2 * i + r];
            hp[2 * i + r] = (1.0f - z) * n + z * hprev;
        }
        __syncthreads();
        // ---- E: logits partials (tid<512) + hid4 partials (all threads)
        if (tid < 512) {
            const int r = tid >> 8, i = tid & 255, m = i & 31, j0 = (i >> 5) * 32;
            const float* wg = g_WgenT + j0 * 32 + m;
            const float* hp = (const float*)h2;
            float p2 = 0;
#pragma unroll 8
            for (int jj = 0; jj < 32; jj++) p2 = fmaf(wg[jj * 32], hp[2 * (j0 + jj) + r], p2);
            scr[tid] = p2;
        }
        {
            const int w = tid >> 5, lane = tid & 31;
            const int r = w >> 4, m = (w >> 2) & 3, qd = w & 3;
            const int j = qd * 32 + lane;
            const float* hp = (const float*)h2;
            float v = g_WlgHT[j * 4 + m] * hp[2 * j + r]
                    + g_WlgHT[(j + 128) * 4 + m] * hp[2 * (j + 128) + r];
            for (int o = 16; o; o >>= 1) v += __shfl_xor_sync(~0u, v, o);
            if (lane == 0) scr[1024 + w] = v;
        }
        __syncthreads();
        // ---- finalize: argmax+probs (warps 0,1), hid4 store (threads 64-71)
        if (tid < 64) {
            const int r = tid >> 5, m = tid & 31;
            float s = bgen_s[m];
#pragma unroll
            for (int g = 0; g < 8; g++) s += scr[r * 256 + m + g * 32];
            float v = (m < 30) ? s : -1e30f;
            float bv = v; int bi = m;
            for (int o = 16; o; o >>= 1) {
                float ov = __shfl_down_sync(~0u, bv, o);
                int   oi = __shfl_down_sync(~0u, bi, o);
                if (ov > bv || (ov == bv && oi < bi)) { bv = ov; bi = oi; }
            }
            bv = __shfl_sync(~0u, bv, 0); bi = __shfl_sync(~0u, bi, 0);
            float ex = (m < 30) ? __expf(v - bv) : 0.0f;
            float sm = ex;
            for (int o = 16; o; o >>= 1) sm += __shfl_xor_sync(~0u, sm, o);
            if (m < 30) probs_out[((size_t)(b0 + r) * TT + t) * 30 + m] = ex / sm;
            if (m == 0) elem_sh[r] = bi;
        } else if (tid < 72) {
            const int r2 = (tid - 64) >> 2, m2 = (tid - 64) & 3;
            float s = 0;
#pragma unroll
            for (int q = 0; q < 4; q++) s += scr[1024 + r2 * 16 + m2 * 4 + q];
            g_hid4[((size_t)(b0 + r2) * TT + t) * 4 + m2] = s;
        }
        __syncthreads();
    }
}

// ---- K3: loc_preds ----
__global__ __launch_bounds__(256) void k3_loc(
    const float* __restrict__ Wlt, const float* __restrict__ blt,
    const float* __restrict__ blg, float* __restrict__ loc_out)
{
    __shared__ float Ps[1024];
    const int b = blockIdx.y, tid = threadIdx.x, lane = tid & 31, w = tid >> 5;
    for (int i = tid; i < 1024; i += 256) Ps[i] = g_P[(size_t)b * 1024 + i];
    __syncthreads();
    int t = blockIdx.x * 8 + w;
    if (t >= TT) return;
    float a0 = 0, a1 = 0, a2 = 0, a3 = 0;
    const float* wp = Wlt + (size_t)t * 256;
    for (int i = 0; i < 8; i++) {
        int l = lane + 32 * i;
        float wv = wp[l];
        float4 p = *(float4*)(Ps + l * 4);
        a0 = fmaf(wv, p.x, a0); a1 = fmaf(wv, p.y, a1);
        a2 = fmaf(wv, p.z, a2); a3 = fmaf(wv, p.w, a3);
    }
    for (int o = 16; o; o >>= 1) {
        a0 += __shfl_xor_sync(~0u, a0, o); a1 += __shfl_xor_sync(~0u, a1, o);
        a2 += __shfl_xor_sync(~0u, a2, o); a3 += __shfl_xor_sync(~0u, a3, o);
    }
    if (lane < 4) {
        float v = (lane == 0) ? a0 : (lane == 1) ? a1 : (lane == 2) ? a2 : a3;
        v += blt[t] * g_S[lane] + blg[lane] + g_hid4[((size_t)b * TT + t) * 4 + lane];
        loc_out[((size_t)b * TT + t) * 4 + lane] = sigm(v);
    }
}

extern "C" void kernel_launch(void* const* d_in, const int* in_sizes, int n_in,
                              void* d_out, int out_size)
{
    const float* fea     = (const float*)d_in[0];
    const float* W_i2h   = (const float*)d_in[1];
    const float* W_h2h   = (const float*)d_in[2];
    const float* b_h2h   = (const float*)d_in[3];
    const float* w_score = (const float*)d_in[4];
    const float* W_ih    = (const float*)d_in[5];
    const float* W_hh    = (const float*)d_in[6];
    const float* b_ih    = (const float*)d_in[7];
    const float* b_hh    = (const float*)d_in[8];
    const float* W_gen   = (const float*)d_in[9];
    const float* b_gen   = (const float*)d_in[10];
    const float* Wlt     = (const float*)d_in[11];
    const float* blt     = (const float*)d_in[12];
    const float* W_lg    = (const float*)d_in[13];
    const float* blg     = (const float*)d_in[14];

    float* out = (float*)d_out;
    float* probs = out;
    float* loc   = out + (size_t)BN * TT * ENM;

    k0_prep<<<256, 256>>>(W_i2h, W_h2h, W_ih, W_hh, W_gen, W_lg);
    kP<<<dim3(32, 128), 256>>>(fea, W_lg);
    k1_gemm<<<dim3(2, 256), 256>>>(fea);
    k2_loop<<<64, 1024>>>(fea, b_h2h, b_ih, b_hh, w_score, b_gen, probs);
    k3_loc<<<dim3(63, 128), 256>>>(Wlt, blt, blg, loc);
}

// round 8
// speedup vs baseline: 1.3616x; 1.3616x over previous
#include <cuda_runtime.h>
#include <cstdint>

#define BN 128
#define TT 501

__device__ __align__(16) float g_Wcat1[512 * 256];
__device__ __align__(16) float g_projT[(size_t)BN * 256 * 256];  // [b][h][l]
__device__ __align__(16) float g_P[BN * 256 * 4];
__device__ float g_S[4];
__device__ float g_hid4[(size_t)BN * TT * 4];
__device__ __align__(16) float g_h[BN * 256];       // [b][j]
__device__ __align__(16) float g_abT[1024 * 128];   // [o][r]
__device__ __align__(16) float g_ctx[BN * 512];     // [b][c]
__device__ __align__(16) float g_giT[768 * 128];    // [k][r]
__device__ volatile unsigned g_barc;

__device__ __forceinline__ float tanhfast(float x) {
    float e, r;
    asm("ex2.approx.f32 %0, %1;" : "=f"(e) : "f"(fabsf(x) * 2.8853900817779268f));
    asm("rcp.approx.f32 %0, %1;" : "=f"(r) : "f"(e + 1.0f));
    return copysignf(1.0f - 2.0f * r, x);
}
__device__ __forceinline__ float sigm(float x) { return 1.0f / (1.0f + __expf(-x)); }

__global__ void kreset() { g_barc = 0u; }

__global__ void k0_prep(const float* __restrict__ W_i2h, const float* __restrict__ W_lg) {
    const int N = 512 * 256;
    for (int i = blockIdx.x * blockDim.x + threadIdx.x; i < N + 4; i += gridDim.x * blockDim.x) {
        if (i < N) { int c = i >> 8, n = i & 255; g_Wcat1[i] = W_i2h[n * 512 + c]; }
        else { int j = i - N; float s = 0.f; for (int c = 0; c < 512; c++) s += W_lg[j * 768 + 256 + c]; g_S[j] = s; }
    }
}

__global__ __launch_bounds__(256) void kP(const float* __restrict__ fea, const float* __restrict__ W_lg) {
    __shared__ float Wl[4 * 512];
    const int b = blockIdx.y, tid = threadIdx.x, lane = tid & 31, w = tid >> 5;
    for (int i = tid; i < 2048; i += 256) Wl[i] = W_lg[(i >> 9) * 768 + 256 + (i & 511)];
    __syncthreads();
    int l = blockIdx.x * 8 + w;
    float a0 = 0, a1 = 0, a2 = 0, a3 = 0;
    const float* fp = fea + ((size_t)(b * 256 + l)) * 512;
    for (int i = 0; i < 16; i++) {
        int c = lane + 32 * i; float f = fp[c];
        a0 = fmaf(f, Wl[c], a0); a1 = fmaf(f, Wl[512 + c], a1);
        a2 = fmaf(f, Wl[1024 + c], a2); a3 = fmaf(f, Wl[1536 + c], a3);
    }
    for (int o = 16; o; o >>= 1) {
        a0 += __shfl_xor_sync(~0u, a0, o); a1 += __shfl_xor_sync(~0u, a1, o);
        a2 += __shfl_xor_sync(~0u, a2, o); a3 += __shfl_xor_sync(~0u, a3, o);
    }
    if (lane < 4) {
        float v = (lane == 0) ? a0 : (lane == 1) ? a1 : (lane == 2) ? a2 : a3;
        g_P[(size_t)(b * 256 + l) * 4 + lane] = v;
    }
}

__global__ __launch_bounds__(256) void k1_gemm(const float* __restrict__ fea) {
    __shared__ float As[16 * 128];
    __shared__ float Bs[16 * 128];
    const int m0 = blockIdx.y * 128, n0 = blockIdx.x * 128;
    const int tid = threadIdx.x, ty = tid >> 4, tx = tid & 15;
    float acc[8][8];
#pragma unroll
    for (int i = 0; i < 8; i++)
#pragma unroll
        for (int j = 0; j < 8; j++) acc[i][j] = 0.f;
    for (int k0 = 0; k0 < 512; k0 += 16) {
#pragma unroll
        for (int s = 0; s < 2; s++) {
            int idx = tid + s * 256, row = idx >> 2, c4 = idx & 3;
            float4 v = *(const float4*)(fea + (size_t)(m0 + row) * 512 + k0 + c4 * 4);
            As[(c4 * 4 + 0) * 128 + row] = v.x; As[(c4 * 4 + 1) * 128 + row] = v.y;
            As[(c4 * 4 + 2) * 128 + row] = v.z; As[(c4 * 4 + 3) * 128 + row] = v.w;
        }
#pragma unroll
        for (int s = 0; s < 2; s++) {
            int idx = tid + s * 256, kk = idx >> 5, n4 = idx & 31;
            *(float4*)(Bs + kk * 128 + n4 * 4) =
                *(const float4*)(g_Wcat1 + (size_t)(k0 + kk) * 256 + n0 + n4 * 4);
        }
        __syncthreads();
#pragma unroll
        for (int kk = 0; kk < 16; kk++) {
            float4 a0 = *(float4*)(As + kk * 128 + ty * 8);
            float4 a1 = *(float4*)(As + kk * 128 + ty * 8 + 4);
            float4 b0 = *(float4*)(Bs + kk * 128 + tx * 8);
            float4 b1 = *(float4*)(Bs + kk * 128 + tx * 8 + 4);
            float av[8] = {a0.x, a0.y, a0.z, a0.w, a1.x, a1.y, a1.z, a1.w};
            float bv[8] = {b0.x, b0.y, b0.z, b0.w, b1.x, b1.y, b1.z, b1.w};
#pragma unroll
            for (int i = 0; i < 8; i++)
#pragma unroll
                for (int j = 0; j < 8; j++) acc[i][j] = fmaf(av[i], bv[j], acc[i][j]);
        }
        __syncthreads();
    }
    const int b = m0 >> 8, l0 = m0 & 255;
#pragma unroll
    for (int i = 0; i < 8; i++)
#pragma unroll
        for (int j = 0; j < 8; j++)
            g_projT[((size_t)b * 256 + n0 + tx * 8 + j) * 256 + l0 + ty * 8 + i] = acc[i][j];
}

// smem offsets (floats)
#define OFF_STG 12384
#define OFF_SCR 28896
#define OFF_QS  30944
#define OFF_ES  31200
#define OFF_WSC 31456
#define OFF_HS  31712
#define OFF_GI  31968
#define OFF_GH  32736
#define OFF_BA  33504
#define OFF_BG  33536
#define SM_FLOATS 33568

__global__ __launch_bounds__(1024, 1) void k2_persist(
    const float* __restrict__ fea,
    const float* __restrict__ Wh2h, const float* __restrict__ bh2h,
    const float* __restrict__ w_score, const float* __restrict__ W_ih,
    const float* __restrict__ Whh, const float* __restrict__ b_ih,
    const float* __restrict__ b_hh, const float* __restrict__ W_gen,
    const float* __restrict__ b_gen, const float* __restrict__ W_lg,
    float* __restrict__ probs)
{
    extern __shared__ __align__(16) float sm[];
    float* wS  = sm;
    float* stg = sm + OFF_STG;
    float* scr = sm + OFF_SCR;
    float* q_s = sm + OFF_QS;
    float* e_s = sm + OFF_ES;
    float* wsc = sm + OFF_WSC;
    float* h_s = sm + OFF_HS;
    float* gis = sm + OFF_GI;
    float* ghs = sm + OFF_GH;
    float* bA  = sm + OFF_BA;
    float* bG  = sm + OFF_BG;
    __shared__ float red[16];
    __shared__ int elem_sh;

    const int b = blockIdx.x, tid = threadIdx.x;
    const int rg = b >> 5, og = b & 31;

    if (tid < 256) { h_s[tid] = 0.f; g_h[b * 256 + tid] = 0.f; wsc[tid] = w_score[tid]; }
    if (tid < 32) {
        int o = og * 32 + tid;
        bA[tid] = (o < 256) ? bh2h[o] : b_hh[o - 256];
        bG[tid] = (tid < 30) ? b_gen[tid] : 0.f;
    }
    if (tid == 0) elem_sh = 0;
    unsigned bt = 128;
    // init barrier
    __syncthreads();
    if (tid == 0) { __threadfence(); atomicAdd((unsigned*)&g_barc, 1u); while (g_barc < bt) {} __threadfence(); }
    __syncthreads();

    for (int t = 0; t < TT; t++) {
        // ===== A: [q|gh](outs og*32..+32) for rows rg*32..+32
        for (int e = tid; e < 8192; e += 1024) {
            int r = e >> 8, j = e & 255;
            stg[r * 260 + j] = g_h[(rg * 32 + r) * 256 + j];
            int o = og * 32 + r;
            wS[r * 260 + j] = (o < 256) ? Wh2h[o * 256 + j] : Whh[(o - 256) * 256 + j];
        }
        __syncthreads();
        {
            const int kh = tid >> 9, rest = tid & 511, op = rest >> 5, r = rest & 31, o0 = op * 2;
            const float* hp = stg + r * 260 + kh * 128;
            const float* w0 = wS + o0 * 260 + kh * 128;
            const float* w1 = w0 + 260;
            float a0 = 0.f, a1 = 0.f;
#pragma unroll
            for (int j = 0; j < 128; j += 4) {
                float4 h4 = *(const float4*)(hp + j);
                float4 wa = *(const float4*)(w0 + j);
                float4 wb = *(const float4*)(w1 + j);
                a0 = fmaf(h4.x, wa.x, a0); a0 = fmaf(h4.y, wa.y, a0);
                a0 = fmaf(h4.z, wa.z, a0); a0 = fmaf(h4.w, wa.w, a0);
                a1 = fmaf(h4.x, wb.x, a1); a1 = fmaf(h4.y, wb.y, a1);
                a1 = fmaf(h4.z, wb.z, a1); a1 = fmaf(h4.w, wb.w, a1);
            }
            scr[kh * 1024 + o0 * 32 + r] = a0;
            scr[kh * 1024 + (o0 + 1) * 32 + r] = a1;
        }
        __syncthreads();
        {
            int o_l = tid >> 5, rr = tid & 31;
            g_abT[(og * 32 + o_l) * 128 + rg * 32 + rr] = scr[tid] + scr[1024 + tid] + bA[o_l];
        }
        __syncthreads();
        if (tid == 0) { __threadfence(); atomicAdd((unsigned*)&g_barc, 1u); bt += 128; while (g_barc < bt) {} __threadfence(); }
        else bt += 128;
        __syncthreads();

        // ===== B: attention + softmax + ctx (row b)
        if (tid < 256) q_s[tid] = g_abT[tid * 128 + b];
        __syncthreads();
        {
            const int l = tid & 255, c = tid >> 8;
            const float* pp = g_projT + ((size_t)b * 256 + c * 64) * 256 + l;
            const float* qq = q_s + c * 64;
            const float* ww = wsc + c * 64;
            float p = 0.f;
#pragma unroll 8
            for (int hh = 0; hh < 64; hh++)
                p = fmaf(ww[hh], tanhfast(pp[(size_t)hh * 256] + qq[hh]), p);
            scr[tid] = p;
        }
        __syncthreads();
        if (tid < 256) {
            float e = scr[tid] + scr[256 + tid] + scr[512 + tid] + scr[768 + tid];
            e_s[tid] = e;
            for (int o = 16; o; o >>= 1) e = fmaxf(e, __shfl_xor_sync(~0u, e, o));
            if ((tid & 31) == 0) red[tid >> 5] = e;
        }
        __syncthreads();
        if (tid < 256) {
            float mx = red[0];
#pragma unroll
            for (int w = 1; w < 8; w++) mx = fmaxf(mx, red[w]);
            float a = __expf(e_s[tid] - mx);
            e_s[tid] = a;
            for (int o = 16; o; o >>= 1) a += __shfl_xor_sync(~0u, a, o);
            if ((tid & 31) == 0) red[8 + (tid >> 5)] = a;
        }
        __syncthreads();
        if (tid < 256) {
            float s = red[8];
#pragma unroll
            for (int w = 1; w < 8; w++) s += red[8 + w];
            e_s[tid] *= (1.f / s);
        }
        __syncthreads();
        {
            const int cp = tid & 255, lq = tid >> 8;
            const float* fp = fea + ((size_t)b * 256 + lq * 64) * 512 + 2 * cp;
            const float* al = e_s + lq * 64;
            float a0 = 0.f, a1 = 0.f;
#pragma unroll 8
            for (int l = 0; l < 64; l++) {
                float2 fv = *(const float2*)(fp + (size_t)l * 512);
                float av = al[l];
                a0 = fmaf(av, fv.x, a0); a1 = fmaf(av, fv.y, a1);
            }
            if (lq) { scr[(lq - 1) * 512 + 2 * cp] = a0; scr[(lq - 1) * 512 + 2 * cp + 1] = a1; }
            __syncthreads();
            if (!lq) {
                a0 += scr[2 * cp] + scr[512 + 2 * cp] + scr[1024 + 2 * cp];
                a1 += scr[2 * cp + 1] + scr[512 + 2 * cp + 1] + scr[1024 + 2 * cp + 1];
                g_ctx[b * 512 + 2 * cp] = a0;
                g_ctx[b * 512 + 2 * cp + 1] = a1;
            }
        }
        __syncthreads();
        if (tid == 0) { __threadfence(); atomicAdd((unsigned*)&g_barc, 1u); bt += 128; while (g_barc < bt) {} __threadfence(); }
        else bt += 128;
        __syncthreads();

        // ===== C: gi(outs og*24..+24) for rows rg*32..+32
        for (int e = tid; e < 16384; e += 1024) {
            int r = e >> 9, c = e & 511;
            stg[r * 516 + c] = g_ctx[(rg * 32 + r) * 512 + c];
        }
        for (int e = tid; e < 12288; e += 1024) {
            int o = e >> 9, c = e & 511;
            wS[o * 516 + c] = W_ih[(size_t)(og * 24 + o) * 542 + c];
        }
        __syncthreads();
        if (tid < 768) {
            const int kh = (tid >= 384) ? 1 : 0;
            const int rest = tid - kh * 384, op = rest >> 5, r = rest & 31, o0 = op * 2;
            const float* cp = stg + r * 516 + kh * 256;
            const float* w0 = wS + o0 * 516 + kh * 256;
            const float* w1 = w0 + 516;
            float a0 = 0.f, a1 = 0.f;
#pragma unroll 8
            for (int j = 0; j < 256; j += 4) {
                float4 c4 = *(const float4*)(cp + j);
                float4 wa = *(const float4*)(w0 + j);
                float4 wb = *(const float4*)(w1 + j);
                a0 = fmaf(c4.x, wa.x, a0); a0 = fmaf(c4.y, wa.y, a0);
                a0 = fmaf(c4.z, wa.z, a0); a0 = fmaf(c4.w, wa.w, a0);
                a1 = fmaf(c4.x, wb.x, a1); a1 = fmaf(c4.y, wb.y, a1);
                a1 = fmaf(c4.z, wb.z, a1); a1 = fmaf(c4.w, wb.w, a1);
            }
            scr[kh * 768 + op * 64 + r] = a0;
            scr[kh * 768 + op * 64 + 32 + r] = a1;
        }
        __syncthreads();
        if (tid < 768) {
            int o_l = tid >> 5, rr = tid & 31;
            int idx = (o_l >> 1) * 64 + (o_l & 1) * 32 + rr;
            g_giT[(og * 24 + o_l) * 128 + rg * 32 + rr] = scr[idx] + scr[768 + idx];
        }
        __syncthreads();
        if (tid == 0) { __threadfence(); atomicAdd((unsigned*)&g_barc, 1u); bt += 128; while (g_barc < bt) {} __threadfence(); }
        else bt += 128;
        __syncthreads();

        // ===== D: GRU + logits/argmax/probs + hid4 (row b)
        {
            const int elem = elem_sh;
            if (tid < 768) {
                gis[tid] = g_giT[tid * 128 + b] + b_ih[tid] + W_ih[(size_t)tid * 542 + 512 + elem];
                ghs[tid] = g_abT[(256 + tid) * 128 + b];
            }
        }
        __syncthreads();
        if (tid < 256) {
            float r = sigm(gis[tid] + ghs[tid]);
            float z = sigm(gis[256 + tid] + ghs[256 + tid]);
            float n = tanhfast(gis[512 + tid] + r * ghs[512 + tid]);
            float h = (1.f - z) * n + z * h_s[tid];
            h_s[tid] = h;
            g_h[b * 256 + tid] = h;
        }
        __syncthreads();
        if (tid < 256) {
            const int m = tid & 31, js = tid >> 5;
            float p = 0.f;
            if (m < 30) {
                const float* wg = W_gen + m * 256 + js * 32;
#pragma unroll 8
                for (int j = 0; j < 32; j++) p = fmaf(wg[j], h_s[js * 32 + j], p);
            }
            scr[tid] = p;
        }
        __syncthreads();
        if (tid < 32) {
            float s = bG[tid];
#pragma unroll
            for (int g = 0; g < 8; g++) s += scr[g * 32 + tid];
            float v = (tid < 30) ? s : -1e30f;
            float bv = v; int bi = tid;
            for (int o = 16; o; o >>= 1) {
                float ov = __shfl_down_sync(~0u, bv, o);
                int oi = __shfl_down_sync(~0u, bi, o);
                if (ov > bv || (ov == bv && oi < bi)) { bv = ov; bi = oi; }
            }
            bv = __shfl_sync(~0u, bv, 0); bi = __shfl_sync(~0u, bi, 0);
            float ex = (tid < 30) ? __expf(v - bv) : 0.f;
            float sm2 = ex;
            for (int o = 16; o; o >>= 1) sm2 += __shfl_xor_sync(~0u, sm2, o);
            if (tid < 30) probs[((size_t)b * TT + t) * 30 + tid] = ex / sm2;
            if (tid == 0) elem_sh = bi;
        } else if (tid < 160) {
            const int m = (tid >> 5) - 1, lane = tid & 31;
            float v = 0.f;
#pragma unroll
            for (int i = 0; i < 8; i++) {
                int j = lane + i * 32;
                v = fmaf(W_lg[m * 768 + j], h_s[j], v);
            }
            for (int o = 16; o; o >>= 1) v += __shfl_xor_sync(~0u, v, o);
            if (lane == 0) g_hid4[((size_t)b * TT + t) * 4 + m] = v;
        }
        __syncthreads();
        if (tid == 0) { __threadfence(); atomicAdd((unsigned*)&g_barc, 1u); bt += 128; while (g_barc < bt) {} __threadfence(); }
        else bt += 128;
        __syncthreads();
    }
}

__global__ __launch_bounds__(256) void k3_loc(const float* __restrict__ Wlt,
    const float* __restrict__ blt, const float* __restrict__ blg, float* __restrict__ loc_out)
{
    __shared__ float Ps[1024];
    const int b = blockIdx.y, tid = threadIdx.x, lane = tid & 31, w = tid >> 5;
    for (int i = tid; i < 1024; i += 256) Ps[i] = g_P[(size_t)b * 1024 + i];
    __syncthreads();
    int t = blockIdx.x * 8 + w;
    if (t >= TT) return;
    float a0 = 0, a1 = 0, a2 = 0, a3 = 0;
    const float* wp = Wlt + (size_t)t * 256;
    for (int i = 0; i < 8; i++) {
        int l = lane + 32 * i;
        float wv = wp[l];
        float4 p = *(float4*)(Ps + l * 4);
        a0 = fmaf(wv, p.x, a0); a1 = fmaf(wv, p.y, a1);
        a2 = fmaf(wv, p.z, a2); a3 = fmaf(wv, p.w, a3);
    }
    for (int o = 16; o; o >>= 1) {
        a0 += __shfl_xor_sync(~0u, a0, o); a1 += __shfl_xor_sync(~0u, a1, o);
        a2 += __shfl_xor_sync(~0u, a2, o); a3 += __shfl_xor_sync(~0u, a3, o);
    }
    if (lane < 4) {
        float v = (lane == 0) ? a0 : (lane == 1) ? a1 : (lane == 2) ? a2 : a3;
        v += blt[t] * g_S[lane] + blg[lane] + g_hid4[((size_t)b * TT + t) * 4 + lane];
        loc_out[((size_t)b * TT + t) * 4 + lane] = sigm(v);
    }
}

extern "C" void kernel_launch(void* const* d_in, const int* in_sizes, int n_in,
                              void* d_out, int out_size)
{
    const float* fea     = (const float*)d_in[0];
    const float* W_i2h   = (const float*)d_in[1];
    const float* W_h2h   = (const float*)d_in[2];
    const float* b_h2h   = (const float*)d_in[3];
    const float* w_score = (const float*)d_in[4];
    const float* W_ih    = (const float*)d_in[5];
    const float* W_hh    = (const float*)d_in[6];
    const float* b_ih    = (const float*)d_in[7];
    const float* b_hh    = (const float*)d_in[8];
    const float* W_gen   = (const float*)d_in[9];
    const float* b_gen   = (const float*)d_in[10];
    const float* Wlt     = (const float*)d_in[11];
    const float* blt     = (const float*)d_in[12];
    const float* W_lg    = (const float*)d_in[13];
    const float* blg     = (const float*)d_in[14];

    float* out = (float*)d_out;
    float* probs = out;
    float* loc   = out + (size_t)BN * TT * 30;

    static int cfg_done = 0;
    if (!cfg_done) {
        cudaFuncSetAttribute(k2_persist, cudaFuncAttributeMaxDynamicSharedMemorySize, SM_FLOATS * 4);
        cfg_done = 1;
    }

    kreset<<<1, 1>>>();
    k0_prep<<<256, 256>>>(W_i2h, W_lg);
    kP<<<dim3(32, 128), 256>>>(fea, W_lg);
    k1_gemm<<<dim3(2, 256), 256>>>(fea);
    k2_persist<<<128, 1024, SM_FLOATS * 4>>>(fea, W_h2h, b_h2h, w_score, W_ih, W_hh,
                                             b_ih, b_hh, W_gen, b_gen, W_lg, probs);
    k3_loc<<<dim3(63, 128), 256>>>(Wlt, blt, blg, loc);
}

// round 11
// speedup vs baseline: 1.4191x; 1.0423x over previous
#include <cuda_runtime.h>
#include <cstdint>

#define BN 128
#define TT 501

__device__ __align__(16) float g_Wcat1[512 * 256];
__device__ __align__(16) float g_Wh2hT[256 * 256];              // [j][i]
__device__ __align__(16) float g_projT[(size_t)BN * 256 * 256]; // [b][h][l]
__device__ __align__(16) float g_P[BN * 256 * 4];
__device__ float g_S[4];
__device__ float g_hid4[(size_t)BN * TT * 4];
__device__ __align__(16) float g_z[BN * 768];       // [b][c]: c<256 h, else ctx
__device__ __align__(16) float g_outT[1024 * 128];  // [o][r]
__device__ volatile unsigned g_barc;

__device__ __forceinline__ float tanhfast(float x) {
    float e, r;
    asm("ex2.approx.f32 %0, %1;" : "=f"(e) : "f"(fabsf(x) * 2.8853900817779268f));
    asm("rcp.approx.f32 %0, %1;" : "=f"(r) : "f"(e + 1.0f));
    return copysignf(1.0f - 2.0f * r, x);
}
__device__ __forceinline__ float sigm(float x) { return 1.0f / (1.0f + __expf(-x)); }

__global__ void kreset() { g_barc = 0u; }

__global__ void k0_prep(const float* __restrict__ W_i2h, const float* __restrict__ W_h2h,
                        const float* __restrict__ W_lg) {
    const int N1 = 512 * 256, N2 = N1 + 256 * 256;
    for (int i = blockIdx.x * blockDim.x + threadIdx.x; i < N2 + 4; i += gridDim.x * blockDim.x) {
        if (i < N1) { int c = i >> 8, n = i & 255; g_Wcat1[i] = W_i2h[n * 512 + c]; }
        else if (i < N2) { int e = i - N1, j = e >> 8, ii = e & 255; g_Wh2hT[e] = W_h2h[ii * 256 + j]; }
        else { int j = i - N2; float s = 0.f; for (int c = 0; c < 512; c++) s += W_lg[j * 768 + 256 + c]; g_S[j] = s; }
    }
}

__global__ __launch_bounds__(256) void kP(const float* __restrict__ fea, const float* __restrict__ W_lg) {
    __shared__ float Wl[4 * 512];
    const int b = blockIdx.y, tid = threadIdx.x, lane = tid & 31, w = tid >> 5;
    for (int i = tid; i < 2048; i += 256) Wl[i] = W_lg[(i >> 9) * 768 + 256 + (i & 511)];
    __syncthreads();
    int l = blockIdx.x * 8 + w;
    float a0 = 0, a1 = 0, a2 = 0, a3 = 0;
    const float* fp = fea + ((size_t)(b * 256 + l)) * 512;
    for (int i = 0; i < 16; i++) {
        int c = lane + 32 * i; float f = fp[c];
        a0 = fmaf(f, Wl[c], a0); a1 = fmaf(f, Wl[512 + c], a1);
        a2 = fmaf(f, Wl[1024 + c], a2); a3 = fmaf(f, Wl[1536 + c], a3);
    }
    for (int o = 16; o; o >>= 1) {
        a0 += __shfl_xor_sync(~0u, a0, o); a1 += __shfl_xor_sync(~0u, a1, o);
        a2 += __shfl_xor_sync(~0u, a2, o); a3 += __shfl_xor_sync(~0u, a3, o);
    }
    if (lane < 4) {
        float v = (lane == 0) ? a0 : (lane == 1) ? a1 : (lane == 2) ? a2 : a3;
        g_P[(size_t)(b * 256 + l) * 4 + lane] = v;
    }
}

__global__ __launch_bounds__(256) void k1_gemm(const float* __restrict__ fea) {
    __shared__ float As[16 * 128];
    __shared__ float Bs[16 * 128];
    const int m0 = blockIdx.y * 128, n0 = blockIdx.x * 128;
    const int tid = threadIdx.x, ty = tid >> 4, tx = tid & 15;
    float acc[8][8];
#pragma unroll
    for (int i = 0; i < 8; i++)
#pragma unroll
        for (int j = 0; j < 8; j++) acc[i][j] = 0.f;
    for (int k0 = 0; k0 < 512; k0 += 16) {
#pragma unroll
        for (int s = 0; s < 2; s++) {
            int idx = tid + s * 256, row = idx >> 2, c4 = idx & 3;
            float4 v = *(const float4*)(fea + (size_t)(m0 + row) * 512 + k0 + c4 * 4);
            As[(c4 * 4 + 0) * 128 + row] = v.x; As[(c4 * 4 + 1) * 128 + row] = v.y;
            As[(c4 * 4 + 2) * 128 + row] = v.z; As[(c4 * 4 + 3) * 128 + row] = v.w;
        }
#pragma unroll
        for (int s = 0; s < 2; s++) {
            int idx = tid + s * 256, kk = idx >> 5, n4 = idx & 31;
            *(float4*)(Bs + kk * 128 + n4 * 4) =
                *(const float4*)(g_Wcat1 + (size_t)(k0 + kk) * 256 + n0 + n4 * 4);
        }
        __syncthreads();
#pragma unroll
        for (int kk = 0; kk < 16; kk++) {
            float4 a0 = *(float4*)(As + kk * 128 + ty * 8);
            float4 a1 = *(float4*)(As + kk * 128 + ty * 8 + 4);
            float4 b0 = *(float4*)(Bs + kk * 128 + tx * 8);
            float4 b1 = *(float4*)(Bs + kk * 128 + tx * 8 + 4);
            float av[8] = {a0.x, a0.y, a0.z, a0.w, a1.x, a1.y, a1.z, a1.w};
            float bv[8] = {b0.x, b0.y, b0.z, b0.w, b1.x, b1.y, b1.z, b1.w};
#pragma unroll
            for (int i = 0; i < 8; i++)
#pragma unroll
                for (int j = 0; j < 8; j++) acc[i][j] = fmaf(av[i], bv[j], acc[i][j]);
        }
        __syncthreads();
    }
    const int b = m0 >> 8, l0 = m0 & 255;
#pragma unroll
    for (int i = 0; i < 8; i++)
#pragma unroll
        for (int j = 0; j < 8; j++)
            g_projT[((size_t)b * 256 + n0 + tx * 8 + j) * 256 + l0 + ty * 8 + i] = acc[i][j];
}

// smem float offsets
#define O_WS   0
#define O_ZS   24704
#define O_SCR  49408
#define O_QS   51456
#define O_ES   51712
#define O_WSC  51968
#define O_HS   52224
#define O_OUT  52480
#define O_OHS  53504
#define O_BIH  54272
#define O_BHH  55040
#define O_BQ   55808
#define O_BG   56064
#define SM_FL  56096

__global__ __launch_bounds__(1024, 1) void k2_persist(
    const float* __restrict__ fea, const float* __restrict__ bh2h,
    const float* __restrict__ w_score, const float* __restrict__ W_ih,
    const float* __restrict__ Whh, const float* __restrict__ b_ih,
    const float* __restrict__ b_hh, const float* __restrict__ W_gen,
    const float* __restrict__ b_gen, const float* __restrict__ W_lg,
    const float* __restrict__ Wh2h, float* __restrict__ probs)
{
    extern __shared__ __align__(16) float sm[];
    float* wS   = sm + O_WS;
    float* zS   = sm + O_ZS;
    float* scr  = sm + O_SCR;
    float* q_s  = sm + O_QS;
    float* e_s  = sm + O_ES;
    float* wsc  = sm + O_WSC;
    float* h_s  = sm + O_HS;
    float* outs = sm + O_OUT;
    float* ohs  = sm + O_OHS;
    float* bih  = sm + O_BIH;
    float* bhh  = sm + O_BHH;
    float* bq   = sm + O_BQ;
    float* bG   = sm + O_BG;
    __shared__ float red[16];
    __shared__ int elem_sh;

    const int b = blockIdx.x, tid = threadIdx.x;
    const int rg = b >> 5, og = b & 31;

    // persistent weight staging for merged GEMM: wS[o_l][k], k<256 h-part, k>=256 ctx-part
    // out layout: o<256 r-gate sum, 256..511 z-gate sum, 512..767 i_n (ctx only), 768..1023 h_n (h only)
    for (int i = tid; i < 32 * 768; i += 1024) {
        int o_l = i / 768, k = i - o_l * 768;
        int o_g = og * 32 + o_l;
        float v;
        if (k < 256) v = (o_g < 512) ? Whh[o_g * 256 + k] : ((o_g >= 768) ? Whh[(o_g - 256) * 256 + k] : 0.f);
        else         v = (o_g < 768) ? W_ih[(size_t)o_g * 542 + (k - 256)] : 0.f;
        wS[o_l * 772 + k] = v;
    }
    if (tid < 256) { h_s[tid] = 0.f; g_z[b * 768 + tid] = 0.f; wsc[tid] = w_score[tid]; bq[tid] = bh2h[tid]; }
    if (tid < 768) { bih[tid] = b_ih[tid]; bhh[tid] = b_hh[tid]; }
    if (tid < 32)  bG[tid] = (tid < 30) ? b_gen[tid] : 0.f;
    if (tid == 0)  elem_sh = 0;
    unsigned bt = 0;
    __syncthreads();

    for (int t = 0; t < TT; t++) {
        // ===== Q: q = W_h2h @ h (row-local, h in smem)
        {
            const int i = tid & 255, c = tid >> 8;
            const float* wp = g_Wh2hT + (size_t)(c * 64) * 256 + i;
            const float* hp = h_s + c * 64;
            float a = 0.f;
#pragma unroll 8
            for (int j = 0; j < 64; j++) a = fmaf(wp[(size_t)j * 256], hp[j], a);
            scr[c * 256 + i] = a;
        }
        __syncthreads();
        if (tid < 256) q_s[tid] = scr[tid] + scr[256 + tid] + scr[512 + tid] + scr[768 + tid] + bq[tid];
        __syncthreads();

        // ===== B: attention scores + softmax + ctx
        {
            const int l = tid & 255, c = tid >> 8;
            const float* pp = g_projT + ((size_t)b * 256 + c * 64) * 256 + l;
            const float* qq = q_s + c * 64;
            const float* ww = wsc + c * 64;
            float p = 0.f;
#pragma unroll 8
            for (int hh = 0; hh < 64; hh++)
                p = fmaf(ww[hh], tanhfast(pp[(size_t)hh * 256] + qq[hh]), p);
            scr[tid] = p;
        }
        __syncthreads();
        if (tid < 256) {
            float e = scr[tid] + scr[256 + tid] + scr[512 + tid] + scr[768 + tid];
            e_s[tid] = e;
            for (int o = 16; o; o >>= 1) e = fmaxf(e, __shfl_xor_sync(~0u, e, o));
            if ((tid & 31) == 0) red[tid >> 5] = e;
        }
        __syncthreads();
        if (tid < 256) {
            float mx = red[0];
#pragma unroll
            for (int w = 1; w < 8; w++) mx = fmaxf(mx, red[w]);
            float a = __expf(e_s[tid] - mx);
            e_s[tid] = a;
            for (int o = 16; o; o >>= 1) a += __shfl_xor_sync(~0u, a, o);
            if ((tid & 31) == 0) red[8 + (tid >> 5)] = a;
        }
        __syncthreads();
        if (tid < 256) {
            float s = red[8];
#pragma unroll
            for (int w = 1; w < 8; w++) s += red[8 + w];
            e_s[tid] *= (1.f / s);
        }
        __syncthreads();
        {
            const int cp = tid & 255, lq = tid >> 8;
            const float* fp = fea + ((size_t)b * 256 + lq * 64) * 512 + 2 * cp;
            const float* al = e_s + lq * 64;
            float a0 = 0.f, a1 = 0.f;
#pragma unroll 8
            for (int l = 0; l < 64; l++) {
                float2 fv = *(const float2*)(fp + (size_t)l * 512);
                float av = al[l];
                a0 = fmaf(av, fv.x, a0); a1 = fmaf(av, fv.y, a1);
            }
            if (lq) { scr[(lq - 1) * 512 + 2 * cp] = a0; scr[(lq - 1) * 512 + 2 * cp + 1] = a1; }
            __syncthreads();
            if (!lq) {
                a0 += scr[2 * cp] + scr[512 + 2 * cp] + scr[1024 + 2 * cp];
                a1 += scr[2 * cp + 1] + scr[512 + 2 * cp + 1] + scr[1024 + 2 * cp + 1];
                g_z[b * 768 + 256 + 2 * cp] = a0;
                g_z[b * 768 + 256 + 2 * cp + 1] = a1;
            }
        }
        // ===== barrier 1 (single counter, proven pattern)
        __syncthreads();
        bt += 128;
        if (tid == 0) {
            __threadfence();
            atomicAdd((unsigned*)&g_barc, 1u);
            while (g_barc < bt) {}
            __threadfence();
        }
        __syncthreads();

        // ===== C': merged GEMM: outs for rows rg*32..+32, outs og*32..+32
        {
            const int w = tid >> 5, lane = tid & 31;
            const float* src = g_z + (size_t)(rg * 32 + w) * 768 + lane * 4;
#pragma unroll
            for (int m = 0; m < 6; m++)
                *(float4*)(zS + w * 772 + lane * 4 + m * 128) = *(const float4*)(src + m * 128);
        }
        __syncthreads();
        {
            const int ks4 = (tid & 15) * 4, tile = tid >> 4;
            const int o0 = (tile & 7) * 4, r0 = (tile >> 3) * 4;
            float acc[4][4] = {};
#pragma unroll
            for (int m = 0; m < 12; m++) {
                int k = ks4 + m * 64;
                float4 wv0 = *(float4*)(wS + (o0 + 0) * 772 + k);
                float4 wv1 = *(float4*)(wS + (o0 + 1) * 772 + k);
                float4 wv2 = *(float4*)(wS + (o0 + 2) * 772 + k);
                float4 wv3 = *(float4*)(wS + (o0 + 3) * 772 + k);
                float4 zv0 = *(float4*)(zS + (r0 + 0) * 772 + k);
                float4 zv1 = *(float4*)(zS + (r0 + 1) * 772 + k);
                float4 zv2 = *(float4*)(zS + (r0 + 2) * 772 + k);
                float4 zv3 = *(float4*)(zS + (r0 + 3) * 772 + k);
                float4 wv[4] = {wv0, wv1, wv2, wv3};
                float4 zv[4] = {zv0, zv1, zv2, zv3};
#pragma unroll
                for (int o = 0; o < 4; o++)
#pragma unroll
                    for (int r = 0; r < 4; r++) {
                        acc[o][r] = fmaf(wv[o].x, zv[r].x, acc[o][r]);
                        acc[o][r] = fmaf(wv[o].y, zv[r].y, acc[o][r]);
                        acc[o][r] = fmaf(wv[o].z, zv[r].z, acc[o][r]);
                        acc[o][r] = fmaf(wv[o].w, zv[r].w, acc[o][r]);
                    }
            }
            __syncthreads();   // z reads done; reuse zS for partials
            const int ks = tid & 15;
#pragma unroll
            for (int o = 0; o < 4; o++)
#pragma unroll
                for (int r = 0; r < 4; r++)
                    zS[ks * 1025 + (o0 + o) * 32 + r0 + r] = acc[o][r];
        }
        __syncthreads();
        {
            const int o_l = tid >> 5, rr = tid & 31;
            float s = 0.f;
#pragma unroll
            for (int ks = 0; ks < 16; ks++) s += zS[ks * 1025 + tid];
            g_outT[(og * 32 + o_l) * 128 + rg * 32 + rr] = s;
        }
        // ===== barrier 2
        __syncthreads();
        bt += 128;
        if (tid == 0) {
            __threadfence();
            atomicAdd((unsigned*)&g_barc, 1u);
            while (g_barc < bt) {}
            __threadfence();
        }
        __syncthreads();

        // ===== D: GRU + logits/argmax/probs + hid4 (row b)
        {
            const int elem = elem_sh;
            outs[tid] = g_outT[tid * 128 + b];
            if (tid < 768) ohs[tid] = W_ih[(size_t)tid * 542 + 512 + elem];
        }
        __syncthreads();
        if (tid < 256) {
            float r = sigm(outs[tid] + bih[tid] + bhh[tid] + ohs[tid]);
            float z = sigm(outs[256 + tid] + bih[256 + tid] + bhh[256 + tid] + ohs[256 + tid]);
            float n = tanhfast(outs[512 + tid] + bih[512 + tid] + ohs[512 + tid]
                               + r * (outs[768 + tid] + bhh[512 + tid]));
            float h = (1.f - z) * n + z * h_s[tid];
            h_s[tid] = h;
            g_z[b * 768 + tid] = h;
        }
        __syncthreads();
        if (tid < 256) {
            const int m = tid & 31, js = tid >> 5;
            float p = 0.f;
            if (m < 30) {
                const float* wg = W_gen + m * 256 + js * 32;
#pragma unroll 8
                for (int j = 0; j < 32; j++) p = fmaf(wg[j], h_s[js * 32 + j], p);
            }
            scr[tid] = p;
        }
        __syncthreads();
        if (tid < 32) {
            float s = bG[tid];
#pragma unroll
            for (int g = 0; g < 8; g++) s += scr[g * 32 + tid];
            float v = (tid < 30) ? s : -1e30f;
            float bv = v; int bi = tid;
            for (int o = 16; o; o >>= 1) {
                float ov = __shfl_down_sync(~0u, bv, o);
                int oi = __shfl_down_sync(~0u, bi, o);
                if (ov > bv || (ov == bv && oi < bi)) { bv = ov; bi = oi; }
            }
            bv = __shfl_sync(~0u, bv, 0); bi = __shfl_sync(~0u, bi, 0);
            float ex = (tid < 30) ? __expf(v - bv) : 0.f;
            float sm2 = ex;
            for (int o = 16; o; o >>= 1) sm2 += __shfl_xor_sync(~0u, sm2, o);
            if (tid < 30) probs[((size_t)b * TT + t) * 30 + tid] = ex / sm2;
            if (tid == 0) elem_sh = bi;
        } else if (tid < 160) {
            const int m = (tid >> 5) - 1, lane = tid & 31;
            float v = 0.f;
#pragma unroll
            for (int i = 0; i < 8; i++) {
                int j = lane + i * 32;
                v = fmaf(W_lg[m * 768 + j], h_s[j], v);
            }
            for (int o = 16; o; o >>= 1) v += __shfl_xor_sync(~0u, v, o);
            if (lane == 0) g_hid4[((size_t)b * TT + t) * 4 + m] = v;
        }
        __syncthreads();
    }
}

__global__ __launch_bounds__(256) void k3_loc(const float* __restrict__ Wlt,
    const float* __restrict__ blt, const float* __restrict__ blg, float* __restrict__ loc_out)
{
    __shared__ float Ps[1024];
    const int b = blockIdx.y, tid = threadIdx.x, lane = tid & 31, w = tid >> 5;
    for (int i = tid; i < 1024; i += 256) Ps[i] = g_P[(size_t)b * 1024 + i];
    __syncthreads();
    int t = blockIdx.x * 8 + w;
    if (t >= TT) return;
    float a0 = 0, a1 = 0, a2 = 0, a3 = 0;
    const float* wp = Wlt + (size_t)t * 256;
    for (int i = 0; i < 8; i++) {
        int l = lane + 32 * i;
        float wv = wp[l];
        float4 p = *(float4*)(Ps + l * 4);
        a0 = fmaf(wv, p.x, a0); a1 = fmaf(wv, p.y, a1);
        a2 = fmaf(wv, p.z, a2); a3 = fmaf(wv, p.w, a3);
    }
    for (int o = 16; o; o >>= 1) {
        a0 += __shfl_xor_sync(~0u, a0, o); a1 += __shfl_xor_sync(~0u, a1, o);
        a2 += __shfl_xor_sync(~0u, a2, o); a3 += __shfl_xor_sync(~0u, a3, o);
    }
    if (lane < 4) {
        float v = (lane == 0) ? a0 : (lane == 1) ? a1 : (lane == 2) ? a2 : a3;
        v += blt[t] * g_S[lane] + blg[lane] + g_hid4[((size_t)b * TT + t) * 4 + lane];
        loc_out[((size_t)b * TT + t) * 4 + lane] = sigm(v);
    }
}

extern "C" void kernel_launch(void* const* d_in, const int* in_sizes, int n_in,
                              void* d_out, int out_size)
{
    const float* fea     = (const float*)d_in[0];
    const float* W_i2h   = (const float*)d_in[1];
    const float* W_h2h   = (const float*)d_in[2];
    const float* b_h2h   = (const float*)d_in[3];
    const float* w_score = (const float*)d_in[4];
    const float* W_ih    = (const float*)d_in[5];
    const float* W_hh    = (const float*)d_in[6];
    const float* b_ih    = (const float*)d_in[7];
    const float* b_hh    = (const float*)d_in[8];
    const float* W_gen   = (const float*)d_in[9];
    const float* b_gen   = (const float*)d_in[10];
    const float* Wlt     = (const float*)d_in[11];
    const float* blt     = (const float*)d_in[12];
    const float* W_lg    = (const float*)d_in[13];
    const float* blg     = (const float*)d_in[14];

    float* out = (float*)d_out;
    float* probs = out;
    float* loc   = out + (size_t)BN * TT * 30;

    static int cfg_done = 0;
    if (!cfg_done) {
        cudaFuncSetAttribute(k2_persist, cudaFuncAttributeMaxDynamicSharedMemorySize, SM_FL * 4);
        cfg_done = 1;
    }

    kreset<<<1, 1>>>();
    k0_prep<<<256, 256>>>(W_i2h, W_h2h, W_lg);
    kP<<<dim3(32, 128), 256>>>(fea, W_lg);
    k1_gemm<<<dim3(2, 256), 256>>>(fea);
    k2_persist<<<128, 1024, SM_FL * 4>>>(fea, b_h2h, w_score, W_ih, W_hh,
                                         b_ih, b_hh, W_gen, b_gen, W_lg, W_h2h, probs);
    k3_loc<<<dim3(63, 128), 256>>>(Wlt, blt, blg, loc);
}

// round 14
// speedup vs baseline: 1.5373x; 1.0833x over previous
#include <cuda_runtime.h>
#include <cstdint>

#define BN 128
#define TT 501

__device__ __align__(16) float g_Wcat1[512 * 256];
__device__ __align__(16) float g_Wh2hT[256 * 256];              // [j][i]
__device__ __align__(16) float g_projT[(size_t)BN * 256 * 256]; // [b][h][l]
__device__ __align__(16) float g_P[BN * 256 * 4];
__device__ __align__(16) float g_OH[30 * 768];                  // [e][k]
__device__ float g_S[4];
__device__ float g_hid4[(size_t)BN * TT * 4];
__device__ __align__(16) float g_z[BN * 768];       // [b][c]: c<256 h, else ctx
__device__ __align__(16) float g_outT[1024 * 128];  // [o][r]
__device__ volatile unsigned g_barg[128];           // 4 group counters at stride 32 (128B)

__device__ __forceinline__ float tanhf2(float x) {
    float e, r;
    asm("ex2.approx.f32 %0, %1;" : "=f"(e) : "f"(fabsf(x) * 2.8853900817779268f));
    asm("rcp.approx.f32 %0, %1;" : "=f"(r) : "f"(e + 1.0f));
    return copysignf(1.0f - 2.0f * r, x);
}
__device__ __forceinline__ float sigm(float x) { return 1.0f / (1.0f + __expf(-x)); }

__global__ void kreset() {
    int i = threadIdx.x;
    if (i < 128) g_barg[i] = 0u;
}

__global__ void k0_prep(const float* __restrict__ W_i2h, const float* __restrict__ W_h2h,
                        const float* __restrict__ W_lg, const float* __restrict__ W_ih) {
    const int N1 = 512 * 256, N2 = N1 + 256 * 256, N3 = N2 + 30 * 768;
    for (int i = blockIdx.x * blockDim.x + threadIdx.x; i < N3 + 4; i += gridDim.x * blockDim.x) {
        if (i < N1) { int c = i >> 8, n = i & 255; g_Wcat1[i] = W_i2h[n * 512 + c]; }
        else if (i < N2) { int e = i - N1, j = e >> 8, ii = e & 255; g_Wh2hT[e] = W_h2h[ii * 256 + j]; }
        else if (i < N3) { int e = i - N2, eo = e / 768, k = e - eo * 768; g_OH[e] = W_ih[(size_t)k * 542 + 512 + eo]; }
        else { int j = i - N3; float s = 0.f; for (int c = 0; c < 512; c++) s += W_lg[j * 768 + 256 + c]; g_S[j] = s; }
    }
}

__global__ __launch_bounds__(256) void kP(const float* __restrict__ fea, const float* __restrict__ W_lg) {
    __shared__ float Wl[4 * 512];
    const int b = blockIdx.y, tid = threadIdx.x, lane = tid & 31, w = tid >> 5;
    for (int i = tid; i < 2048; i += 256) Wl[i] = W_lg[(i >> 9) * 768 + 256 + (i & 511)];
    __syncthreads();
    int l = blockIdx.x * 8 + w;
    float a0 = 0, a1 = 0, a2 = 0, a3 = 0;
    const float* fp = fea + ((size_t)(b * 256 + l)) * 512;
    for (int i = 0; i < 16; i++) {
        int c = lane + 32 * i; float f = fp[c];
        a0 = fmaf(f, Wl[c], a0); a1 = fmaf(f, Wl[512 + c], a1);
        a2 = fmaf(f, Wl[1024 + c], a2); a3 = fmaf(f, Wl[1536 + c], a3);
    }
    for (int o = 16; o; o >>= 1) {
        a0 += __shfl_xor_sync(~0u, a0, o); a1 += __shfl_xor_sync(~0u, a1, o);
        a2 += __shfl_xor_sync(~0u, a2, o); a3 += __shfl_xor_sync(~0u, a3, o);
    }
    if (lane < 4) {
        float v = (lane == 0) ? a0 : (lane == 1) ? a1 : (lane == 2) ? a2 : a3;
        g_P[(size_t)(b * 256 + l) * 4 + lane] = v;
    }
}

__global__ __launch_bounds__(256) void k1_gemm(const float* __restrict__ fea) {
    __shared__ float As[16 * 128];
    __shared__ float Bs[16 * 128];
    const int m0 = blockIdx.y * 128, n0 = blockIdx.x * 128;
    const int tid = threadIdx.x, ty = tid >> 4, tx = tid & 15;
    float acc[8][8];
#pragma unroll
    for (int i = 0; i < 8; i++)
#pragma unroll
        for (int j = 0; j < 8; j++) acc[i][j] = 0.f;
    for (int k0 = 0; k0 < 512; k0 += 16) {
#pragma unroll
        for (int s = 0; s < 2; s++) {
            int idx = tid + s * 256, row = idx >> 2, c4 = idx & 3;
            float4 v = *(const float4*)(fea + (size_t)(m0 + row) * 512 + k0 + c4 * 4);
            As[(c4 * 4 + 0) * 128 + row] = v.x; As[(c4 * 4 + 1) * 128 + row] = v.y;
            As[(c4 * 4 + 2) * 128 + row] = v.z; As[(c4 * 4 + 3) * 128 + row] = v.w;
        }
#pragma unroll
        for (int s = 0; s < 2; s++) {
            int idx = tid + s * 256, kk = idx >> 5, n4 = idx & 31;
            *(float4*)(Bs + kk * 128 + n4 * 4) =
                *(const float4*)(g_Wcat1 + (size_t)(k0 + kk) * 256 + n0 + n4 * 4);
        }
        __syncthreads();
#pragma unroll
        for (int kk = 0; kk < 16; kk++) {
            float4 a0 = *(float4*)(As + kk * 128 + ty * 8);
            float4 a1 = *(float4*)(As + kk * 128 + ty * 8 + 4);
            float4 b0 = *(float4*)(Bs + kk * 128 + tx * 8);
            float4 b1 = *(float4*)(Bs + kk * 128 + tx * 8 + 4);
            float av[8] = {a0.x, a0.y, a0.z, a0.w, a1.x, a1.y, a1.z, a1.w};
            float bv[8] = {b0.x, b0.y, b0.z, b0.w, b1.x, b1.y, b1.z, b1.w};
#pragma unroll
            for (int i = 0; i < 8; i++)
#pragma unroll
                for (int j = 0; j < 8; j++) acc[i][j] = fmaf(av[i], bv[j], acc[i][j]);
        }
        __syncthreads();
    }
    const int b = m0 >> 8, l0 = m0 & 255;
#pragma unroll
    for (int i = 0; i < 8; i++)
#pragma unroll
        for (int j = 0; j < 8; j++)
            g_projT[((size_t)b * 256 + n0 + tx * 8 + j) * 256 + l0 + ty * 8 + i] = acc[i][j];
}

// smem float offsets
#define O_WS   0
#define O_ZS   24704
#define O_SCR  49408
#define O_QS   51456
#define O_ES   51712
#define O_WSC  51968
#define O_HS   52224
#define O_OUT  52480
#define O_OHS  53504
#define O_BIH  54272
#define O_BHH  55040
#define O_BQ   55808
#define O_BG   56064
#define SM_FL  56096

__global__ __launch_bounds__(1024, 1) void k2_persist(
    const float* __restrict__ fea, const float* __restrict__ bh2h,
    const float* __restrict__ w_score, const float* __restrict__ W_ih,
    const float* __restrict__ Whh, const float* __restrict__ b_ih,
    const float* __restrict__ b_hh, const float* __restrict__ W_gen,
    const float* __restrict__ b_gen, const float* __restrict__ W_lg,
    float* __restrict__ probs)
{
    extern __shared__ __align__(16) float sm[];
    float* wS   = sm + O_WS;
    float* zS   = sm + O_ZS;
    float* scr  = sm + O_SCR;
    float* q_s  = sm + O_QS;
    float* e_s  = sm + O_ES;
    float* wsc  = sm + O_WSC;
    float* h_s  = sm + O_HS;
    float* outs = sm + O_OUT;
    float* ohs  = sm + O_OHS;
    float* bih  = sm + O_BIH;
    float* bhh  = sm + O_BHH;
    float* bq   = sm + O_BQ;
    float* bG   = sm + O_BG;
    __shared__ float red[16];
    __shared__ int elem_sh;

    const int b = blockIdx.x, tid = threadIdx.x;
    const int rg = b >> 5, og = b & 31;
    volatile unsigned* barp = &g_barg[rg * 32];

    for (int i = tid; i < 32 * 768; i += 1024) {
        int o_l = i / 768, k = i - o_l * 768;
        int o_g = og * 32 + o_l;
        float v;
        if (k < 256) v = (o_g < 512) ? Whh[o_g * 256 + k] : ((o_g >= 768) ? Whh[(o_g - 256) * 256 + k] : 0.f);
        else         v = (o_g < 768) ? W_ih[(size_t)o_g * 542 + (k - 256)] : 0.f;
        wS[o_l * 772 + k] = v;
    }
    if (tid < 256) { h_s[tid] = 0.f; g_z[b * 768 + tid] = 0.f; wsc[tid] = w_score[tid]; bq[tid] = bh2h[tid]; }
    if (tid < 768) { bih[tid] = b_ih[tid]; bhh[tid] = b_hh[tid]; }
    if (tid < 32)  bG[tid] = (tid < 30) ? b_gen[tid] : 0.f;
    if (tid == 0)  elem_sh = 0;
    unsigned bt = 0;
    __syncthreads();

    for (int t = 0; t < TT; t++) {
        // ===== Q: q = W_h2h @ h (row-local)
        {
            const int i = tid & 255, c = tid >> 8;
            const float* wp = g_Wh2hT + (size_t)(c * 64) * 256 + i;
            const float* hp = h_s + c * 64;
            float a = 0.f;
#pragma unroll 8
            for (int j = 0; j < 64; j++) a = fmaf(wp[(size_t)j * 256], hp[j], a);
            scr[c * 256 + i] = a;
        }
        __syncthreads();
        if (tid < 256) q_s[tid] = scr[tid] + scr[256 + tid] + scr[512 + tid] + scr[768 + tid] + bq[tid];
        __syncthreads();

        // ===== B: attention + softmax + ctx
        {
            const int l = tid & 255, c = tid >> 8;
            const float* pp = g_projT + ((size_t)b * 256 + c * 64) * 256 + l;
            const float* qq = q_s + c * 64;
            const float* ww = wsc + c * 64;
            float p = 0.f;
#pragma unroll 8
            for (int hh = 0; hh < 64; hh++)
                p = fmaf(ww[hh], tanhf2(pp[(size_t)hh * 256] + qq[hh]), p);
            scr[tid] = p;
        }
        __syncthreads();
        if (tid < 256) {
            float e = scr[tid] + scr[256 + tid] + scr[512 + tid] + scr[768 + tid];
            e_s[tid] = e;
            for (int o = 16; o; o >>= 1) e = fmaxf(e, __shfl_xor_sync(~0u, e, o));
            if ((tid & 31) == 0) red[tid >> 5] = e;
        }
        __syncthreads();
        if (tid < 256) {
            float mx = red[0];
#pragma unroll
            for (int w = 1; w < 8; w++) mx = fmaxf(mx, red[w]);
            float a = __expf(e_s[tid] - mx);
            e_s[tid] = a;
            for (int o = 16; o; o >>= 1) a += __shfl_xor_sync(~0u, a, o);
            if ((tid & 31) == 0) red[8 + (tid >> 5)] = a;
        }
        __syncthreads();
        if (tid < 256) {
            float s = red[8];
#pragma unroll
            for (int w = 1; w < 8; w++) s += red[8 + w];
            e_s[tid] *= (1.f / s);
        }
        __syncthreads();
        {
            const int cp = tid & 255, lq = tid >> 8;
            const float* fp = fea + ((size_t)b * 256 + lq * 64) * 512 + 2 * cp;
            const float* al = e_s + lq * 64;
            float a0 = 0.f, a1 = 0.f;
#pragma unroll 8
            for (int l = 0; l < 64; l++) {
                float2 fv = *(const float2*)(fp + (size_t)l * 512);
                float av = al[l];
                a0 = fmaf(av, fv.x, a0); a1 = fmaf(av, fv.y, a1);
            }
            if (lq) { scr[(lq - 1) * 512 + 2 * cp] = a0; scr[(lq - 1) * 512 + 2 * cp + 1] = a1; }
            __syncthreads();
            if (!lq) {
                a0 += scr[2 * cp] + scr[512 + 2 * cp] + scr[1024 + 2 * cp];
                a1 += scr[2 * cp + 1] + scr[512 + 2 * cp + 1] + scr[1024 + 2 * cp + 1];
                g_z[b * 768 + 256 + 2 * cp] = a0;
                g_z[b * 768 + 256 + 2 * cp + 1] = a1;
            }
        }
        // ===== barrier 1 (row-group local: 32 arrivals, with back-off)
        __syncthreads();
        bt += 32;
        if (tid == 0) {
            __threadfence();
            atomicAdd((unsigned*)barp, 1u);
            while (*barp < bt) { __nanosleep(64); }
            __threadfence();
        }
        __syncthreads();

        // ===== C': merged GEMM
        {
            const int w = tid >> 5, lane = tid & 31;
            const float* src = g_z + (size_t)(rg * 32 + w) * 768 + lane * 4;
#pragma unroll
            for (int m = 0; m < 6; m++)
                *(float4*)(zS + w * 772 + lane * 4 + m * 128) = *(const float4*)(src + m * 128);
        }
        __syncthreads();
        {
            const int ks4 = (tid & 15) * 4, tile = tid >> 4;
            const int o0 = (tile & 7) * 4, r0 = (tile >> 3) * 4;
            float acc[4][4] = {};
#pragma unroll
            for (int m = 0; m < 12; m++) {
                int k = ks4 + m * 64;
                float4 wv0 = *(float4*)(wS + (o0 + 0) * 772 + k);
                float4 wv1 = *(float4*)(wS + (o0 + 1) * 772 + k);
                float4 wv2 = *(float4*)(wS + (o0 + 2) * 772 + k);
                float4 wv3 = *(float4*)(wS + (o0 + 3) * 772 + k);
                float4 zv0 = *(float4*)(zS + (r0 + 0) * 772 + k);
                float4 zv1 = *(float4*)(zS + (r0 + 1) * 772 + k);
                float4 zv2 = *(float4*)(zS + (r0 + 2) * 772 + k);
                float4 zv3 = *(float4*)(zS + (r0 + 3) * 772 + k);
                float4 wv[4] = {wv0, wv1, wv2, wv3};
                float4 zv[4] = {zv0, zv1, zv2, zv3};
#pragma unroll
                for (int o = 0; o < 4; o++)
#pragma unroll
                    for (int r = 0; r < 4; r++) {
                        acc[o][r] = fmaf(wv[o].x, zv[r].x, acc[o][r]);
                        acc[o][r] = fmaf(wv[o].y, zv[r].y, acc[o][r]);
                        acc[o][r] = fmaf(wv[o].z, zv[r].z, acc[o][r]);
                        acc[o][r] = fmaf(wv[o].w, zv[r].w, acc[o][r]);
                    }
            }
            __syncthreads();
            const int ks = tid & 15;
#pragma unroll
            for (int o = 0; o < 4; o++)
#pragma unroll
                for (int r = 0; r < 4; r++)
                    zS[ks * 1025 + (o0 + o) * 32 + r0 + r] = acc[o][r];
        }
        __syncthreads();
        {
            const int o_l = tid >> 5, rr = tid & 31;
            float s = 0.f;
#pragma unroll
            for (int ks = 0; ks < 16; ks++) s += zS[ks * 1025 + tid];
            g_outT[(og * 32 + o_l) * 128 + rg * 32 + rr] = s;
        }
        // ===== barrier 2 (row-group local)
        __syncthreads();
        bt += 32;
        if (tid == 0) {
            __threadfence();
            atomicAdd((unsigned*)barp, 1u);
            while (*barp < bt) { __nanosleep(64); }
            __threadfence();
        }
        __syncthreads();

        // ===== D: GRU + logits/argmax/probs + hid4
        {
            const int elem = elem_sh;
            outs[tid] = g_outT[tid * 128 + b];
            if (tid < 768) ohs[tid] = g_OH[elem * 768 + tid];
        }
        __syncthreads();
        if (tid < 256) {
            float r = sigm(outs[tid] + bih[tid] + bhh[tid] + ohs[tid]);
            float z = sigm(outs[256 + tid] + bih[256 + tid] + bhh[256 + tid] + ohs[256 + tid]);
            float n = tanhf2(outs[512 + tid] + bih[512 + tid] + ohs[512 + tid]
                             + r * (outs[768 + tid] + bhh[512 + tid]));
            float h = (1.f - z) * n + z * h_s[tid];
            h_s[tid] = h;
            g_z[b * 768 + tid] = h;
        }
        __syncthreads();
        if (tid < 256) {
            const int m = tid & 31, js = tid >> 5;
            float p = 0.f;
            if (m < 30) {
                const float* wg = W_gen + m * 256 + js * 32;
#pragma unroll 8
                for (int j = 0; j < 32; j++) p = fmaf(wg[j], h_s[js * 32 + j], p);
            }
            scr[tid] = p;
        }
        __syncthreads();
        if (tid < 32) {
            float s = bG[tid];
#pragma unroll
            for (int g = 0; g < 8; g++) s += scr[g * 32 + tid];
            float v = (tid < 30) ? s : -1e30f;
            float bv = v; int bi = tid;
            for (int o = 16; o; o >>= 1) {
                float ov = __shfl_down_sync(~0u, bv, o);
                int oi = __shfl_down_sync(~0u, bi, o);
                if (ov > bv || (ov == bv && oi < bi)) { bv = ov; bi = oi; }
            }
            bv = __shfl_sync(~0u, bv, 0); bi = __shfl_sync(~0u, bi, 0);
            float ex = (tid < 30) ? __expf(v - bv) : 0.f;
            float sm2 = ex;
            for (int o = 16; o; o >>= 1) sm2 += __shfl_xor_sync(~0u, sm2, o);
            if (tid < 30) probs[((size_t)b * TT + t) * 30 + tid] = ex / sm2;
            if (tid == 0) elem_sh = bi;
        } else if (tid < 160) {
            const int m = (tid >> 5) - 1, lane = tid & 31;
            float v = 0.f;
#pragma unroll
            for (int i = 0; i < 8; i++) {
                int j = lane + i * 32;
                v = fmaf(W_lg[m * 768 + j], h_s[j], v);
            }
            for (int o = 16; o; o >>= 1) v += __shfl_xor_sync(~0u, v, o);
            if (lane == 0) g_hid4[((size_t)b * TT + t) * 4 + m] = v;
        }
        __syncthreads();
    }
}

__global__ __launch_bounds__(256) void k3_loc(const float* __restrict__ Wlt,
    const float* __restrict__ blt, const float* __restrict__ blg, float* __restrict__ loc_out)
{
    __shared__ float Ps[1024];
    const int b = blockIdx.y, tid = threadIdx.x, lane = tid & 31, w = tid >> 5;
    for (int i = tid; i < 1024; i += 256) Ps[i] = g_P[(size_t)b * 1024 + i];
    __syncthreads();
    int t = blockIdx.x * 8 + w;
    if (t >= TT) return;
    float a0 = 0, a1 = 0, a2 = 0, a3 = 0;
    const float* wp = Wlt + (size_t)t * 256;
    for (int i = 0; i < 8; i++) {
        int l = lane + 32 * i;
        float wv = wp[l];
        float4 p = *(float4*)(Ps + l * 4);
        a0 = fmaf(wv, p.x, a0); a1 = fmaf(wv, p.y, a1);
        a2 = fmaf(wv, p.z, a2); a3 = fmaf(wv, p.w, a3);
    }
    for (int o = 16; o; o >>= 1) {
        a0 += __shfl_xor_sync(~0u, a0, o); a1 += __shfl_xor_sync(~0u, a1, o);
        a2 += __shfl_xor_sync(~0u, a2, o); a3 += __shfl_xor_sync(~0u, a3, o);
    }
    if (lane < 4) {
        float v = (lane == 0) ? a0 : (lane == 1) ? a1 : (lane == 2) ? a2 : a3;
        v += blt[t] * g_S[lane] + blg[lane] + g_hid4[((size_t)b * TT + t) * 4 + lane];
        loc_out[((size_t)b * TT + t) * 4 + lane] = sigm(v);
    }
}

extern "C" void kernel_launch(void* const* d_in, const int* in_sizes, int n_in,
                              void* d_out, int out_size)
{
    const float* fea     = (const float*)d_in[0];
    const float* W_i2h   = (const float*)d_in[1];
    const float* W_h2h   = (const float*)d_in[2];
    const float* b_h2h   = (const float*)d_in[3];
    const float* w_score = (const float*)d_in[4];
    const float* W_ih    = (const float*)d_in[5];
    const float* W_hh    = (const float*)d_in[6];
    const float* b_ih    = (const float*)d_in[7];
    const float* b_hh    = (const float*)d_in[8];
    const float* W_gen   = (const float*)d_in[9];
    const float* b_gen   = (const float*)d_in[10];
    const float* Wlt     = (const float*)d_in[11];
    const float* blt     = (const float*)d_in[12];
    const float* W_lg    = (const float*)d_in[13];
    const float* blg     = (const float*)d_in[14];

    float* out = (float*)d_out;
    float* probs = out;
    float* loc   = out + (size_t)BN * TT * 30;

    static int cfg_done = 0;
    if (!cfg_done) {
        cudaFuncSetAttribute(k2_persist, cudaFuncAttributeMaxDynamicSharedMemorySize, SM_FL * 4);
        cfg_done = 1;
    }

    kreset<<<1, 128>>>();
    k0_prep<<<256, 256>>>(W_i2h, W_h2h, W_lg, W_ih);
    kP<<<dim3(32, 128), 256>>>(fea, W_lg);
    k1_gemm<<<dim3(2, 256), 256>>>(fea);
    k2_persist<<<128, 1024, SM_FL * 4>>>(fea, b_h2h, w_score, W_ih, W_hh,
                                         b_ih, b_hh, W_gen, b_gen, W_lg, probs);
    k3_loc<<<dim3(63, 128), 256>>>(Wlt, blt, blg, loc);
}

// round 15
// speedup vs baseline: 1.7584x; 1.1438x over previous
#include <cuda_runtime.h>
#include <cstdint>

#define BN 128
#define TT 501

__device__ __align__(16) float g_Wcat1[512 * 256];
__device__ __align__(16) float g_Wh2hT[256 * 256];              // [j][i]
__device__ __align__(16) float g_projT[(size_t)BN * 256 * 256]; // [b][h][l]
__device__ __align__(16) float g_P[BN * 256 * 4];
__device__ __align__(16) float g_OH[30 * 768];                  // [e][k]
__device__ float g_S[4];
__device__ float g_hid4[(size_t)BN * TT * 4];
__device__ __align__(16) float g_z[BN * 768];       // [b][c]: c<256 h, else ctx
__device__ __align__(16) float g_outT[1024 * 128];  // [o][r]
__device__ volatile unsigned g_barg[128];           // 4 group counters at stride 32 (128B)

__device__ __forceinline__ float tanhf2(float x) {
    float e, r;
    asm("ex2.approx.f32 %0, %1;" : "=f"(e) : "f"(fabsf(x) * 2.8853900817779268f));
    asm("rcp.approx.f32 %0, %1;" : "=f"(r) : "f"(e + 1.0f));
    return copysignf(1.0f - 2.0f * r, x);
}
__device__ __forceinline__ float tanha(float x) {
    float y; asm("tanh.approx.f32 %0, %1;" : "=f"(y) : "f"(x)); return y;
}
__device__ __forceinline__ float sigm(float x) { return 1.0f / (1.0f + __expf(-x)); }

__global__ void kreset() {
    int i = threadIdx.x;
    if (i < 128) g_barg[i] = 0u;
}

__global__ void k0_prep(const float* __restrict__ W_i2h, const float* __restrict__ W_h2h,
                        const float* __restrict__ W_lg, const float* __restrict__ W_ih) {
    const int N1 = 512 * 256, N2 = N1 + 256 * 256, N3 = N2 + 30 * 768;
    for (int i = blockIdx.x * blockDim.x + threadIdx.x; i < N3 + 4; i += gridDim.x * blockDim.x) {
        if (i < N1) { int c = i >> 8, n = i & 255; g_Wcat1[i] = W_i2h[n * 512 + c]; }
        else if (i < N2) { int e = i - N1, j = e >> 8, ii = e & 255; g_Wh2hT[e] = W_h2h[ii * 256 + j]; }
        else if (i < N3) { int e = i - N2, eo = e / 768, k = e - eo * 768; g_OH[e] = W_ih[(size_t)k * 542 + 512 + eo]; }
        else { int j = i - N3; float s = 0.f; for (int c = 0; c < 512; c++) s += W_lg[j * 768 + 256 + c]; g_S[j] = s; }
    }
}

__global__ __launch_bounds__(256) void kP(const float* __restrict__ fea, const float* __restrict__ W_lg) {
    __shared__ float Wl[4 * 512];
    const int b = blockIdx.y, tid = threadIdx.x, lane = tid & 31, w = tid >> 5;
    for (int i = tid; i < 2048; i += 256) Wl[i] = W_lg[(i >> 9) * 768 + 256 + (i & 511)];
    __syncthreads();
    int l = blockIdx.x * 8 + w;
    float a0 = 0, a1 = 0, a2 = 0, a3 = 0;
    const float* fp = fea + ((size_t)(b * 256 + l)) * 512;
    for (int i = 0; i < 16; i++) {
        int c = lane + 32 * i; float f = fp[c];
        a0 = fmaf(f, Wl[c], a0); a1 = fmaf(f, Wl[512 + c], a1);
        a2 = fmaf(f, Wl[1024 + c], a2); a3 = fmaf(f, Wl[1536 + c], a3);
    }
    for (int o = 16; o; o >>= 1) {
        a0 += __shfl_xor_sync(~0u, a0, o); a1 += __shfl_xor_sync(~0u, a1, o);
        a2 += __shfl_xor_sync(~0u, a2, o); a3 += __shfl_xor_sync(~0u, a3, o);
    }
    if (lane < 4) {
        float v = (lane == 0) ? a0 : (lane == 1) ? a1 : (lane == 2) ? a2 : a3;
        g_P[(size_t)(b * 256 + l) * 4 + lane] = v;
    }
}

__global__ __launch_bounds__(256) void k1_gemm(const float* __restrict__ fea) {
    __shared__ float As[16 * 128];
    __shared__ float Bs[16 * 128];
    const int m0 = blockIdx.y * 128, n0 = blockIdx.x * 128;
    const int tid = threadIdx.x, ty = tid >> 4, tx = tid & 15;
    float acc[8][8];
#pragma unroll
    for (int i = 0; i < 8; i++)
#pragma unroll
        for (int j = 0; j < 8; j++) acc[i][j] = 0.f;
    for (int k0 = 0; k0 < 512; k0 += 16) {
#pragma unroll
        for (int s = 0; s < 2; s++) {
            int idx = tid + s * 256, row = idx >> 2, c4 = idx & 3;
            float4 v = *(const float4*)(fea + (size_t)(m0 + row) * 512 + k0 + c4 * 4);
            As[(c4 * 4 + 0) * 128 + row] = v.x; As[(c4 * 4 + 1) * 128 + row] = v.y;
            As[(c4 * 4 + 2) * 128 + row] = v.z; As[(c4 * 4 + 3) * 128 + row] = v.w;
        }
#pragma unroll
        for (int s = 0; s < 2; s++) {
            int idx = tid + s * 256, kk = idx >> 5, n4 = idx & 31;
            *(float4*)(Bs + kk * 128 + n4 * 4) =
                *(const float4*)(g_Wcat1 + (size_t)(k0 + kk) * 256 + n0 + n4 * 4);
        }
        __syncthreads();
#pragma unroll
        for (int kk = 0; kk < 16; kk++) {
            float4 a0 = *(float4*)(As + kk * 128 + ty * 8);
            float4 a1 = *(float4*)(As + kk * 128 + ty * 8 + 4);
            float4 b0 = *(float4*)(Bs + kk * 128 + tx * 8);
            float4 b1 = *(float4*)(Bs + kk * 128 + tx * 8 + 4);
            float av[8] = {a0.x, a0.y, a0.z, a0.w, a1.x, a1.y, a1.z, a1.w};
            float bv[8] = {b0.x, b0.y, b0.z, b0.w, b1.x, b1.y, b1.z, b1.w};
#pragma unroll
            for (int i = 0; i < 8; i++)
#pragma unroll
                for (int j = 0; j < 8; j++) acc[i][j] = fmaf(av[i], bv[j], acc[i][j]);
        }
        __syncthreads();
    }
    const int b = m0 >> 8, l0 = m0 & 255;
#pragma unroll
    for (int i = 0; i < 8; i++)
#pragma unroll
        for (int j = 0; j < 8; j++)
            g_projT[((size_t)b * 256 + n0 + tx * 8 + j) * 256 + l0 + ty * 8 + i] = acc[i][j];
}

// smem float offsets
#define O_WS   0
#define O_ZS   24704
#define O_SCR  49408
#define O_QS   51456
#define O_ES   51712
#define O_WSC  51968
#define O_HS   52224
#define O_OUT  52480
#define O_OHS  53504
#define O_BIH  54272
#define O_BHH  55040
#define O_BQ   55808
#define O_BG   56064
#define SM_FL  56096

__global__ __launch_bounds__(1024, 1) void k2_persist(
    const float* __restrict__ fea, const float* __restrict__ bh2h,
    const float* __restrict__ w_score, const float* __restrict__ W_ih,
    const float* __restrict__ Whh, const float* __restrict__ b_ih,
    const float* __restrict__ b_hh, const float* __restrict__ W_gen,
    const float* __restrict__ b_gen, const float* __restrict__ W_lg,
    float* __restrict__ probs)
{
    extern __shared__ __align__(16) float sm[];
    float* wS   = sm + O_WS;
    float* zS   = sm + O_ZS;
    float* scr  = sm + O_SCR;
    float* q_s  = sm + O_QS;
    float* e_s  = sm + O_ES;
    float* wsc  = sm + O_WSC;
    float* h_s  = sm + O_HS;
    float* outs = sm + O_OUT;
    float* ohs  = sm + O_OHS;
    float* bih  = sm + O_BIH;
    float* bhh  = sm + O_BHH;
    float* bq   = sm + O_BQ;
    float* bG   = sm + O_BG;
    __shared__ float red[16];
    __shared__ int elem_sh;

    const int b = blockIdx.x, tid = threadIdx.x;
    const int rg = b >> 5, og = b & 31;
    volatile unsigned* barp = &g_barg[rg * 32];

    for (int i = tid; i < 32 * 768; i += 1024) {
        int o_l = i / 768, k = i - o_l * 768;
        int o_g = og * 32 + o_l;
        float v;
        if (k < 256) v = (o_g < 512) ? Whh[o_g * 256 + k] : ((o_g >= 768) ? Whh[(o_g - 256) * 256 + k] : 0.f);
        else         v = (o_g < 768) ? W_ih[(size_t)o_g * 542 + (k - 256)] : 0.f;
        wS[o_l * 772 + k] = v;
    }
    if (tid < 256) { h_s[tid] = 0.f; g_z[b * 768 + tid] = 0.f; wsc[tid] = w_score[tid]; bq[tid] = bh2h[tid]; }
    if (tid < 768) { bih[tid] = b_ih[tid]; bhh[tid] = b_hh[tid]; }
    if (tid < 32)  bG[tid] = (tid < 30) ? b_gen[tid] : 0.f;
    if (tid == 0)  elem_sh = 0;
    unsigned bt = 0;
    __syncthreads();

    for (int t = 0; t < TT; t++) {
        // ===== Q: q = W_h2h @ h (row-local, float4 weight loads, 16-way j-split)
        {
            const int c = tid >> 6, i4 = tid & 63;           // c: j-split, i4: output quad
            const float* wp = g_Wh2hT + (size_t)(c * 16) * 256 + i4 * 4;
            const float* hp = h_s + c * 16;
            float a0 = 0.f, a1 = 0.f, a2 = 0.f, a3 = 0.f;
#pragma unroll
            for (int jj = 0; jj < 16; jj++) {
                float4 w4 = *(const float4*)(wp + (size_t)jj * 256);
                float hv = hp[jj];
                a0 = fmaf(w4.x, hv, a0); a1 = fmaf(w4.y, hv, a1);
                a2 = fmaf(w4.z, hv, a2); a3 = fmaf(w4.w, hv, a3);
            }
            *(float4*)(zS + c * 256 + i4 * 4) = make_float4(a0, a1, a2, a3);
        }
        __syncthreads();
        if (tid < 256) {
            float q = bq[tid];
#pragma unroll
            for (int c = 0; c < 16; c++) q += zS[c * 256 + tid];
            q_s[tid] = q;
        }
        __syncthreads();

        // ===== B: attention (MUFU.TANH) + softmax + ctx
        {
            const int l = tid & 255, c = tid >> 8;
            const float* pp = g_projT + ((size_t)b * 256 + c * 64) * 256 + l;
            const float* qq = q_s + c * 64;
            const float* ww = wsc + c * 64;
            float p = 0.f;
#pragma unroll 8
            for (int hh = 0; hh < 64; hh++)
                p = fmaf(ww[hh], tanha(pp[(size_t)hh * 256] + qq[hh]), p);
            scr[tid] = p;
        }
        __syncthreads();
        if (tid < 256) {
            float e = scr[tid] + scr[256 + tid] + scr[512 + tid] + scr[768 + tid];
            e_s[tid] = e;
            for (int o = 16; o; o >>= 1) e = fmaxf(e, __shfl_xor_sync(~0u, e, o));
            if ((tid & 31) == 0) red[tid >> 5] = e;
        }
        __syncthreads();
        if (tid < 256) {
            float mx = red[0];
#pragma unroll
            for (int w = 1; w < 8; w++) mx = fmaxf(mx, red[w]);
            float a = __expf(e_s[tid] - mx);
            e_s[tid] = a;
            for (int o = 16; o; o >>= 1) a += __shfl_xor_sync(~0u, a, o);
            if ((tid & 31) == 0) red[8 + (tid >> 5)] = a;
        }
        __syncthreads();
        if (tid < 256) {
            float s = red[8];
#pragma unroll
            for (int w = 1; w < 8; w++) s += red[8 + w];
            e_s[tid] *= (1.f / s);
        }
        __syncthreads();
        {
            const int cp = tid & 255, lq = tid >> 8;
            const float* fp = fea + ((size_t)b * 256 + lq * 64) * 512 + 2 * cp;
            const float* al = e_s + lq * 64;
            float a0 = 0.f, a1 = 0.f;
#pragma unroll 8
            for (int l = 0; l < 64; l++) {
                float2 fv = *(const float2*)(fp + (size_t)l * 512);
                float av = al[l];
                a0 = fmaf(av, fv.x, a0); a1 = fmaf(av, fv.y, a1);
            }
            if (lq) { scr[(lq - 1) * 512 + 2 * cp] = a0; scr[(lq - 1) * 512 + 2 * cp + 1] = a1; }
            __syncthreads();
            if (!lq) {
                a0 += scr[2 * cp] + scr[512 + 2 * cp] + scr[1024 + 2 * cp];
                a1 += scr[2 * cp + 1] + scr[512 + 2 * cp + 1] + scr[1024 + 2 * cp + 1];
                g_z[b * 768 + 256 + 2 * cp] = a0;
                g_z[b * 768 + 256 + 2 * cp + 1] = a1;
            }
        }
        // ===== barrier 1 (row-group local)
        __syncthreads();
        bt += 32;
        if (tid == 0) {
            __threadfence();
            atomicAdd((unsigned*)barp, 1u);
            while (*barp < bt) { __nanosleep(64); }
            __threadfence();
        }
        __syncthreads();

        // ===== C': merged GEMM
        {
            const int w = tid >> 5, lane = tid & 31;
            const float* src = g_z + (size_t)(rg * 32 + w) * 768 + lane * 4;
#pragma unroll
            for (int m = 0; m < 6; m++)
                *(float4*)(zS + w * 772 + lane * 4 + m * 128) = *(const float4*)(src + m * 128);
        }
        __syncthreads();
        {
            const int ks4 = (tid & 15) * 4, tile = tid >> 4;
            const int o0 = (tile & 7) * 4, r0 = (tile >> 3) * 4;
            float acc[4][4] = {};
#pragma unroll
            for (int m = 0; m < 12; m++) {
                int k = ks4 + m * 64;
                float4 wv0 = *(float4*)(wS + (o0 + 0) * 772 + k);
                float4 wv1 = *(float4*)(wS + (o0 + 1) * 772 + k);
                float4 wv2 = *(float4*)(wS + (o0 + 2) * 772 + k);
                float4 wv3 = *(float4*)(wS + (o0 + 3) * 772 + k);
                float4 zv0 = *(float4*)(zS + (r0 + 0) * 772 + k);
                float4 zv1 = *(float4*)(zS + (r0 + 1) * 772 + k);
                float4 zv2 = *(float4*)(zS + (r0 + 2) * 772 + k);
                float4 zv3 = *(float4*)(zS + (r0 + 3) * 772 + k);
                float4 wv[4] = {wv0, wv1, wv2, wv3};
                float4 zv[4] = {zv0, zv1, zv2, zv3};
#pragma unroll
                for (int o = 0; o < 4; o++)
#pragma unroll
                    for (int r = 0; r < 4; r++) {
                        acc[o][r] = fmaf(wv[o].x, zv[r].x, acc[o][r]);
                        acc[o][r] = fmaf(wv[o].y, zv[r].y, acc[o][r]);
                        acc[o][r] = fmaf(wv[o].z, zv[r].z, acc[o][r]);
                        acc[o][r] = fmaf(wv[o].w, zv[r].w, acc[o][r]);
                    }
            }
            __syncthreads();
            const int ks = tid & 15;
#pragma unroll
            for (int o = 0; o < 4; o++)
#pragma unroll
                for (int r = 0; r < 4; r++)
                    zS[ks * 1025 + (o0 + o) * 32 + r0 + r] = acc[o][r];
        }
        __syncthreads();
        {
            const int o_l = tid >> 5, rr = tid & 31;
            float s = 0.f;
#pragma unroll
            for (int ks = 0; ks < 16; ks++) s += zS[ks * 1025 + tid];
            g_outT[(og * 32 + o_l) * 128 + rg * 32 + rr] = s;
        }
        // ===== barrier 2 (row-group local)
        __syncthreads();
        bt += 32;
        if (tid == 0) {
            __threadfence();
            atomicAdd((unsigned*)barp, 1u);
            while (*barp < bt) { __nanosleep(64); }
            __threadfence();
        }
        __syncthreads();

        // ===== D: GRU + logits/argmax/probs + hid4
        {
            const int elem = elem_sh;
            outs[tid] = g_outT[tid * 128 + b];
            if (tid < 768) ohs[tid] = g_OH[elem * 768 + tid];
        }
        __syncthreads();
        if (tid < 256) {
            float r = sigm(outs[tid] + bih[tid] + bhh[tid] + ohs[tid]);
            float z = sigm(outs[256 + tid] + bih[256 + tid] + bhh[256 + tid] + ohs[256 + tid]);
            float n = tanhf2(outs[512 + tid] + bih[512 + tid] + ohs[512 + tid]
                             + r * (outs[768 + tid] + bhh[512 + tid]));
            float h = (1.f - z) * n + z * h_s[tid];
            h_s[tid] = h;
            g_z[b * 768 + tid] = h;
        }
        __syncthreads();
        if (tid < 256) {
            const int m = tid & 31, js = tid >> 5;
            float p = 0.f;
            if (m < 30) {
                const float* wg = W_gen + m * 256 + js * 32;
#pragma unroll 8
                for (int j = 0; j < 32; j++) p = fmaf(wg[j], h_s[js * 32 + j], p);
            }
            scr[tid] = p;
        }
        __syncthreads();
        if (tid < 32) {
            float s = bG[tid];
#pragma unroll
            for (int g = 0; g < 8; g++) s += scr[g * 32 + tid];
            float v = (tid < 30) ? s : -1e30f;
            float bv = v; int bi = tid;
            for (int o = 16; o; o >>= 1) {
                float ov = __shfl_down_sync(~0u, bv, o);
                int oi = __shfl_down_sync(~0u, bi, o);
                if (ov > bv || (ov == bv && oi < bi)) { bv = ov; bi = oi; }
            }
            bv = __shfl_sync(~0u, bv, 0); bi = __shfl_sync(~0u, bi, 0);
            float ex = (tid < 30) ? __expf(v - bv) : 0.f;
            float sm2 = ex;
            for (int o = 16; o; o >>= 1) sm2 += __shfl_xor_sync(~0u, sm2, o);
            if (tid < 30) probs[((size_t)b * TT + t) * 30 + tid] = ex / sm2;
            if (tid == 0) elem_sh = bi;
        } else if (tid < 160) {
            const int m = (tid >> 5) - 1, lane = tid & 31;
            float v = 0.f;
#pragma unroll
            for (int i = 0; i < 8; i++) {
                int j = lane + i * 32;
                v = fmaf(W_lg[m * 768 + j], h_s[j], v);
            }
            for (int o = 16; o; o >>= 1) v += __shfl_xor_sync(~0u, v, o);
            if (lane == 0) g_hid4[((size_t)b * TT + t) * 4 + m] = v;
        }
        __syncthreads();
    }
}

__global__ __launch_bounds__(256) void k3_loc(const float* __restrict__ Wlt,
    const float* __restrict__ blt, const float* __restrict__ blg, float* __restrict__ loc_out)
{
    __shared__ float Ps[1024];
    const int b = blockIdx.y, tid = threadIdx.x, lane = tid & 31, w = tid >> 5;
    for (int i = tid; i < 1024; i += 256) Ps[i] = g_P[(size_t)b * 1024 + i];
    __syncthreads();
    int t = blockIdx.x * 8 + w;
    if (t >= TT) return;
    float a0 = 0, a1 = 0, a2 = 0, a3 = 0;
    const float* wp = Wlt + (size_t)t * 256;
    for (int i = 0; i < 8; i++) {
        int l = lane + 32 * i;
        float wv = wp[l];
        float4 p = *(float4*)(Ps + l * 4);
        a0 = fmaf(wv, p.x, a0); a1 = fmaf(wv, p.y, a1);
        a2 = fmaf(wv, p.z, a2); a3 = fmaf(wv, p.w, a3);
    }
    for (int o = 16; o; o >>= 1) {
        a0 += __shfl_xor_sync(~0u, a0, o); a1 += __shfl_xor_sync(~0u, a1, o);
        a2 += __shfl_xor_sync(~0u, a2, o); a3 += __shfl_xor_sync(~0u, a3, o);
    }
    if (lane < 4) {
        float v = (lane == 0) ? a0 : (lane == 1) ? a1 : (lane == 2) ? a2 : a3;
        v += blt[t] * g_S[lane] + blg[lane] + g_hid4[((size_t)b * TT + t) * 4 + lane];
        loc_out[((size_t)b * TT + t) * 4 + lane] = sigm(v);
    }
}

extern "C" void kernel_launch(void* const* d_in, const int* in_sizes, int n_in,
                              void* d_out, int out_size)
{
    const float* fea     = (const float*)d_in[0];
    const float* W_i2h   = (const float*)d_in[1];
    const float* W_h2h   = (const float*)d_in[2];
    const float* b_h2h   = (const float*)d_in[3];
    const float* w_score = (const float*)d_in[4];
    const float* W_ih    = (const float*)d_in[5];
    const float* W_hh    = (const float*)d_in[6];
    const float* b_ih    = (const float*)d_in[7];
    const float* b_hh    = (const float*)d_in[8];
    const float* W_gen   = (const float*)d_in[9];
    const float* b_gen   = (const float*)d_in[10];
    const float* Wlt     = (const float*)d_in[11];
    const float* blt     = (const float*)d_in[12];
    const float* W_lg    = (const float*)d_in[13];
    const float* blg     = (const float*)d_in[14];

    float* out = (float*)d_out;
    float* probs = out;
    float* loc   = out + (size_t)BN * TT * 30;

    static int cfg_done = 0;
    if (!cfg_done) {
        cudaFuncSetAttribute(k2_persist, cudaFuncAttributeMaxDynamicSharedMemorySize, SM_FL * 4);
        cfg_done = 1;
    }

    kreset<<<1, 128>>>();
    k0_prep<<<256, 256>>>(W_i2h, W_h2h, W_lg, W_ih);
    kP<<<dim3(32, 128), 256>>>(fea, W_lg);
    k1_gemm<<<dim3(2, 256), 256>>>(fea);
    k2_persist<<<128, 1024, SM_FL * 4>>>(fea, b_h2h, w_score, W_ih, W_hh,
                                         b_ih, b_hh, W_gen, b_gen, W_lg, probs);
    k3_loc<<<dim3(63, 128), 256>>>(Wlt, blt, blg, loc);
}

// round 17
// speedup vs baseline: 1.8452x; 1.0493x over previous
#include <cuda_runtime.h>
#include <cstdint>

#define BN 128
#define TT 501

__device__ __align__(16) float g_Wcat1[512 * 256];
__device__ __align__(16) float g_Wh2hT[256 * 256];              // [j][i]
__device__ __align__(16) float g_projT[(size_t)BN * 256 * 256]; // [b][h][l]
__device__ __align__(16) float g_P[BN * 256 * 4];
__device__ __align__(16) float g_OH[30 * 768];                  // [e][k]
__device__ float g_S[4];
__device__ float g_hid4[(size_t)BN * TT * 4];
__device__ __align__(16) float g_z[BN * 768];       // [b][c]: c<256 h, else ctx
__device__ __align__(16) float g_out[128 * 1024];   // [r][o]  (transposed vs R15)
__device__ volatile unsigned g_barg[128];           // 4 group counters at stride 32 (128B)

__device__ __forceinline__ float tanhf2(float x) {
    float e, r;
    asm("ex2.approx.f32 %0, %1;" : "=f"(e) : "f"(fabsf(x) * 2.8853900817779268f));
    asm("rcp.approx.f32 %0, %1;" : "=f"(r) : "f"(e + 1.0f));
    return copysignf(1.0f - 2.0f * r, x);
}
__device__ __forceinline__ float tanha(float x) {
    float y; asm("tanh.approx.f32 %0, %1;" : "=f"(y) : "f"(x)); return y;
}
__device__ __forceinline__ float sigm(float x) { return 1.0f / (1.0f + __expf(-x)); }

__global__ void kreset() {
    int i = threadIdx.x;
    if (i < 128) g_barg[i] = 0u;
}

__global__ void k0_prep(const float* __restrict__ W_i2h, const float* __restrict__ W_h2h,
                        const float* __restrict__ W_lg, const float* __restrict__ W_ih) {
    const int N1 = 512 * 256, N2 = N1 + 256 * 256, N3 = N2 + 30 * 768;
    for (int i = blockIdx.x * blockDim.x + threadIdx.x; i < N3 + 4; i += gridDim.x * blockDim.x) {
        if (i < N1) { int c = i >> 8, n = i & 255; g_Wcat1[i] = W_i2h[n * 512 + c]; }
        else if (i < N2) { int e = i - N1, j = e >> 8, ii = e & 255; g_Wh2hT[e] = W_h2h[ii * 256 + j]; }
        else if (i < N3) { int e = i - N2, eo = e / 768, k = e - eo * 768; g_OH[e] = W_ih[(size_t)k * 542 + 512 + eo]; }
        else { int j = i - N3; float s = 0.f; for (int c = 0; c < 512; c++) s += W_lg[j * 768 + 256 + c]; g_S[j] = s; }
    }
}

__global__ __launch_bounds__(256) void kP(const float* __restrict__ fea, const float* __restrict__ W_lg) {
    __shared__ float Wl[4 * 512];
    const int b = blockIdx.y, tid = threadIdx.x, lane = tid & 31, w = tid >> 5;
    for (int i = tid; i < 2048; i += 256) Wl[i] = W_lg[(i >> 9) * 768 + 256 + (i & 511)];
    __syncthreads();
    int l = blockIdx.x * 8 + w;
    float a0 = 0, a1 = 0, a2 = 0, a3 = 0;
    const float* fp = fea + ((size_t)(b * 256 + l)) * 512;
    for (int i = 0; i < 16; i++) {
        int c = lane + 32 * i; float f = fp[c];
        a0 = fmaf(f, Wl[c], a0); a1 = fmaf(f, Wl[512 + c], a1);
        a2 = fmaf(f, Wl[1024 + c], a2); a3 = fmaf(f, Wl[1536 + c], a3);
    }
    for (int o = 16; o; o >>= 1) {
        a0 += __shfl_xor_sync(~0u, a0, o); a1 += __shfl_xor_sync(~0u, a1, o);
        a2 += __shfl_xor_sync(~0u, a2, o); a3 += __shfl_xor_sync(~0u, a3, o);
    }
    if (lane < 4) {
        float v = (lane == 0) ? a0 : (lane == 1) ? a1 : (lane == 2) ? a2 : a3;
        g_P[(size_t)(b * 256 + l) * 4 + lane] = v;
    }
}

__global__ __launch_bounds__(256) void k1_gemm(const float* __restrict__ fea) {
    __shared__ float As[16 * 128];
    __shared__ float Bs[16 * 128];
    const int m0 = blockIdx.y * 128, n0 = blockIdx.x * 128;
    const int tid = threadIdx.x, ty = tid >> 4, tx = tid & 15;
    float acc[8][8];
#pragma unroll
    for (int i = 0; i < 8; i++)
#pragma unroll
        for (int j = 0; j < 8; j++) acc[i][j] = 0.f;
    for (int k0 = 0; k0 < 512; k0 += 16) {
#pragma unroll
        for (int s = 0; s < 2; s++) {
            int idx = tid + s * 256, row = idx >> 2, c4 = idx & 3;
            float4 v = *(const float4*)(fea + (size_t)(m0 + row) * 512 + k0 + c4 * 4);
            As[(c4 * 4 + 0) * 128 + row] = v.x; As[(c4 * 4 + 1) * 128 + row] = v.y;
            As[(c4 * 4 + 2) * 128 + row] = v.z; As[(c4 * 4 + 3) * 128 + row] = v.w;
        }
#pragma unroll
        for (int s = 0; s < 2; s++) {
            int idx = tid + s * 256, kk = idx >> 5, n4 = idx & 31;
            *(float4*)(Bs + kk * 128 + n4 * 4) =
                *(const float4*)(g_Wcat1 + (size_t)(k0 + kk) * 256 + n0 + n4 * 4);
        }
        __syncthreads();
#pragma unroll
        for (int kk = 0; kk < 16; kk++) {
            float4 a0 = *(float4*)(As + kk * 128 + ty * 8);
            float4 a1 = *(float4*)(As + kk * 128 + ty * 8 + 4);
            float4 b0 = *(float4*)(Bs + kk * 128 + tx * 8);
            float4 b1 = *(float4*)(Bs + kk * 128 + tx * 8 + 4);
            float av[8] = {a0.x, a0.y, a0.z, a0.w, a1.x, a1.y, a1.z, a1.w};
            float bv[8] = {b0.x, b0.y, b0.z, b0.w, b1.x, b1.y, b1.z, b1.w};
#pragma unroll
            for (int i = 0; i < 8; i++)
#pragma unroll
                for (int j = 0; j < 8; j++) acc[i][j] = fmaf(av[i], bv[j], acc[i][j]);
        }
        __syncthreads();
    }
    const int b = m0 >> 8, l0 = m0 & 255;
#pragma unroll
    for (int i = 0; i < 8; i++)
#pragma unroll
        for (int j = 0; j < 8; j++)
            g_projT[((size_t)b * 256 + n0 + tx * 8 + j) * 256 + l0 + ty * 8 + i] = acc[i][j];
}

// smem float offsets
#define O_WS   0
#define O_ZS   24704
#define O_SCR  49408
#define O_QS   51456
#define O_ES   51712
#define O_WSC  51968
#define O_HS   52224
#define O_OUT  52480
#define O_OHS  53504
#define O_BIH  54272
#define O_BHH  55040
#define O_BQ   55808
#define O_BG   56064
#define SM_FL  56096

__global__ __launch_bounds__(1024, 1) void k2_persist(
    const float* __restrict__ fea, const float* __restrict__ bh2h,
    const float* __restrict__ w_score, const float* __restrict__ W_ih,
    const float* __restrict__ Whh, const float* __restrict__ b_ih,
    const float* __restrict__ b_hh, const float* __restrict__ W_gen,
    const float* __restrict__ b_gen, const float* __restrict__ W_lg,
    float* __restrict__ probs)
{
    extern __shared__ __align__(16) float sm[];
    float* wS   = sm + O_WS;
    float* zS   = sm + O_ZS;
    float* scr  = sm + O_SCR;
    float* q_s  = sm + O_QS;
    float* e_s  = sm + O_ES;
    float* wsc  = sm + O_WSC;
    float* h_s  = sm + O_HS;
    float* outs = sm + O_OUT;
    float* ohs  = sm + O_OHS;
    float* bih  = sm + O_BIH;
    float* bhh  = sm + O_BHH;
    float* bq   = sm + O_BQ;
    float* bG   = sm + O_BG;
    __shared__ float red[16];
    __shared__ int elem_sh;

    const int b = blockIdx.x, tid = threadIdx.x;
    const int rg = b >> 5, og = b & 31;
    volatile unsigned* barp = &g_barg[rg * 32];

    for (int i = tid; i < 32 * 768; i += 1024) {
        int o_l = i / 768, k = i - o_l * 768;
        int o_g = og * 32 + o_l;
        float v;
        if (k < 256) v = (o_g < 512) ? Whh[o_g * 256 + k] : ((o_g >= 768) ? Whh[(o_g - 256) * 256 + k] : 0.f);
        else         v = (o_g < 768) ? W_ih[(size_t)o_g * 542 + (k - 256)] : 0.f;
        wS[o_l * 772 + k] = v;
    }
    if (tid < 256) { h_s[tid] = 0.f; g_z[b * 768 + tid] = 0.f; wsc[tid] = w_score[tid]; bq[tid] = bh2h[tid]; }
    if (tid < 768) { bih[tid] = b_ih[tid]; bhh[tid] = b_hh[tid]; }
    if (tid < 32)  bG[tid] = (tid < 30) ? b_gen[tid] : 0.f;
    if (tid == 0)  elem_sh = 0;
    unsigned bt = 0;
    __syncthreads();

    for (int t = 0; t < TT; t++) {
        // ===== Q: q = W_h2h @ h (row-local, float4 weight loads, 16-way j-split)
        {
            const int c = tid >> 6, i4 = tid & 63;
            const float* wp = g_Wh2hT + (size_t)(c * 16) * 256 + i4 * 4;
            const float* hp = h_s + c * 16;
            float a0 = 0.f, a1 = 0.f, a2 = 0.f, a3 = 0.f;
#pragma unroll
            for (int jj = 0; jj < 16; jj++) {
                float4 w4 = *(const float4*)(wp + (size_t)jj * 256);
                float hv = hp[jj];
                a0 = fmaf(w4.x, hv, a0); a1 = fmaf(w4.y, hv, a1);
                a2 = fmaf(w4.z, hv, a2); a3 = fmaf(w4.w, hv, a3);
            }
            *(float4*)(zS + c * 256 + i4 * 4) = make_float4(a0, a1, a2, a3);
        }
        __syncthreads();
        if (tid < 256) {
            float q = bq[tid];
#pragma unroll
            for (int c = 0; c < 16; c++) q += zS[c * 256 + tid];
            q_s[tid] = q;
        }
        __syncthreads();

        // ===== B: attention (MUFU.TANH) + softmax (no max pass; |e|<=~10) + ctx (fp32)
        {
            const int l = tid & 255, c = tid >> 8;
            const float* pp = g_projT + ((size_t)b * 256 + c * 64) * 256 + l;
            const float* qq = q_s + c * 64;
            const float* ww = wsc + c * 64;
            float p = 0.f;
#pragma unroll 8
            for (int hh = 0; hh < 64; hh++)
                p = fmaf(ww[hh], tanha(pp[(size_t)hh * 256] + qq[hh]), p);
            scr[tid] = p;
        }
        __syncthreads();
        if (tid < 256) {
            float e = scr[tid] + scr[256 + tid] + scr[512 + tid] + scr[768 + tid];
            float a = __expf(e);
            e_s[tid] = a;
            for (int o = 16; o; o >>= 1) a += __shfl_xor_sync(~0u, a, o);
            if ((tid & 31) == 0) red[tid >> 5] = a;
        }
        __syncthreads();
        if (tid < 256) {
            float s = red[0];
#pragma unroll
            for (int w = 1; w < 8; w++) s += red[w];
            e_s[tid] *= (1.f / s);
        }
        __syncthreads();
        {
            const int cp = tid & 255, lq = tid >> 8;
            const float* fp = fea + ((size_t)b * 256 + lq * 64) * 512 + 2 * cp;
            const float* al = e_s + lq * 64;
            float a0 = 0.f, a1 = 0.f;
#pragma unroll 8
            for (int l = 0; l < 64; l++) {
                float2 fv = *(const float2*)(fp + (size_t)l * 512);
                float av = al[l];
                a0 = fmaf(av, fv.x, a0); a1 = fmaf(av, fv.y, a1);
            }
            if (lq) { scr[(lq - 1) * 512 + 2 * cp] = a0; scr[(lq - 1) * 512 + 2 * cp + 1] = a1; }
            __syncthreads();
            if (!lq) {
                a0 += scr[2 * cp] + scr[512 + 2 * cp] + scr[1024 + 2 * cp];
                a1 += scr[2 * cp + 1] + scr[512 + 2 * cp + 1] + scr[1024 + 2 * cp + 1];
                g_z[b * 768 + 256 + 2 * cp] = a0;
                g_z[b * 768 + 256 + 2 * cp + 1] = a1;
            }
        }
        // ===== barrier 1 (row-group local)
        __syncthreads();
        bt += 32;
        if (tid == 0) {
            __threadfence();
            atomicAdd((unsigned*)barp, 1u);
            while (*barp < bt) { __nanosleep(64); }
            __threadfence();
        }
        __syncthreads();

        // ===== C': merged GEMM
        {
            const int w = tid >> 5, lane = tid & 31;
            const float* src = g_z + (size_t)(rg * 32 + w) * 768 + lane * 4;
#pragma unroll
            for (int m = 0; m < 6; m++)
                *(float4*)(zS + w * 772 + lane * 4 + m * 128) = *(const float4*)(src + m * 128);
        }
        __syncthreads();
        {
            const int ks4 = (tid & 15) * 4, tile = tid >> 4;
            const int o0 = (tile & 7) * 4, r0 = (tile >> 3) * 4;
            float acc[4][4] = {};
#pragma unroll
            for (int m = 0; m < 12; m++) {
                int k = ks4 + m * 64;
                float4 wv0 = *(float4*)(wS + (o0 + 0) * 772 + k);
                float4 wv1 = *(float4*)(wS + (o0 + 1) * 772 + k);
                float4 wv2 = *(float4*)(wS + (o0 + 2) * 772 + k);
                float4 wv3 = *(float4*)(wS + (o0 + 3) * 772 + k);
                float4 zv0 = *(float4*)(zS + (r0 + 0) * 772 + k);
                float4 zv1 = *(float4*)(zS + (r0 + 1) * 772 + k);
                float4 zv2 = *(float4*)(zS + (r0 + 2) * 772 + k);
                float4 zv3 = *(float4*)(zS + (r0 + 3) * 772 + k);
                float4 wv[4] = {wv0, wv1, wv2, wv3};
                float4 zv[4] = {zv0, zv1, zv2, zv3};
#pragma unroll
                for (int o = 0; o < 4; o++)
#pragma unroll
                    for (int r = 0; r < 4; r++) {
                        acc[o][r] = fmaf(wv[o].x, zv[r].x, acc[o][r]);
                        acc[o][r] = fmaf(wv[o].y, zv[r].y, acc[o][r]);
                        acc[o][r] = fmaf(wv[o].z, zv[r].z, acc[o][r]);
                        acc[o][r] = fmaf(wv[o].w, zv[r].w, acc[o][r]);
                    }
            }
            __syncthreads();
            const int ks = tid & 15;
#pragma unroll
            for (int o = 0; o < 4; o++)
#pragma unroll
                for (int r = 0; r < 4; r++)
                    zS[ks * 1025 + (o0 + o) * 32 + r0 + r] = acc[o][r];
        }
        __syncthreads();
        {
            const int o_l = tid >> 5, rr = tid & 31;
            float s = 0.f;
#pragma unroll
            for (int ks = 0; ks < 16; ks++) s += zS[ks * 1025 + tid];
            g_out[(size_t)(rg * 32 + rr) * 1024 + og * 32 + o_l] = s;   // [r][o] coalesced-read layout
        }
        // ===== barrier 2 (row-group local)
        __syncthreads();
        bt += 32;
        if (tid == 0) {
            __threadfence();
            atomicAdd((unsigned*)barp, 1u);
            while (*barp < bt) { __nanosleep(64); }
            __threadfence();
        }
        __syncthreads();

        // ===== D: GRU + logits/argmax/probs + hid4 (coalesced out read)
        {
            const int elem = elem_sh;
            outs[tid] = g_out[(size_t)b * 1024 + tid];
            if (tid < 768) ohs[tid] = g_OH[elem * 768 + tid];
        }
        __syncthreads();
        if (tid < 256) {
            float r = sigm(outs[tid] + bih[tid] + bhh[tid] + ohs[tid]);
            float z = sigm(outs[256 + tid] + bih[256 + tid] + bhh[256 + tid] + ohs[256 + tid]);
            float n = tanhf2(outs[512 + tid] + bih[512 + tid] + ohs[512 + tid]
                             + r * (outs[768 + tid] + bhh[512 + tid]));
            float h = (1.f - z) * n + z * h_s[tid];
            h_s[tid] = h;
            g_z[b * 768 + tid] = h;
        }
        __syncthreads();
        if (tid < 256) {
            const int m = tid & 31, js = tid >> 5;
            float p = 0.f;
            if (m < 30) {
                const float* wg = W_gen + m * 256 + js * 32;
#pragma unroll 8
                for (int j = 0; j < 32; j++) p = fmaf(wg[j], h_s[js * 32 + j], p);
            }
            scr[tid] = p;
        }
        __syncthreads();
        if (tid < 32) {
            float s = bG[tid];
#pragma unroll
            for (int g = 0; g < 8; g++) s += scr[g * 32 + tid];
            float v = (tid < 30) ? s : -1e30f;
            float bv = v; int bi = tid;
            for (int o = 16; o; o >>= 1) {
                float ov = __shfl_down_sync(~0u, bv, o);
                int oi = __shfl_down_sync(~0u, bi, o);
                if (ov > bv || (ov == bv && oi < bi)) { bv = ov; bi = oi; }
            }
            bv = __shfl_sync(~0u, bv, 0); bi = __shfl_sync(~0u, bi, 0);
            float ex = (tid < 30) ? __expf(v - bv) : 0.f;
            float sm2 = ex;
            for (int o = 16; o; o >>= 1) sm2 += __shfl_xor_sync(~0u, sm2, o);
            if (tid < 30) probs[((size_t)b * TT + t) * 30 + tid] = ex / sm2;
            if (tid == 0) elem_sh = bi;
        } else if (tid < 160) {
            const int m = (tid >> 5) - 1, lane = tid & 31;
            float v = 0.f;
#pragma unroll
            for (int i = 0; i < 8; i++) {
                int j = lane + i * 32;
                v = fmaf(W_lg[m * 768 + j], h_s[j], v);
            }
            for (int o = 16; o; o >>= 1) v += __shfl_xor_sync(~0u, v, o);
            if (lane == 0) g_hid4[((size_t)b * TT + t) * 4 + m] = v;
        }
        __syncthreads();
    }
}

__global__ __launch_bounds__(256) void k3_loc(const float* __restrict__ Wlt,
    const float* __restrict__ blt, const float* __restrict__ blg, float* __restrict__ loc_out)
{
    __shared__ float Ps[1024];
    const int b = blockIdx.y, tid = threadIdx.x, lane = tid & 31, w = tid >> 5;
    for (int i = tid; i < 1024; i += 256) Ps[i] = g_P[(size_t)b * 1024 + i];
    __syncthreads();
    int t = blockIdx.x * 8 + w;
    if (t >= TT) return;
    float a0 = 0, a1 = 0, a2 = 0, a3 = 0;
    const float* wp = Wlt + (size_t)t * 256;
    for (int i = 0; i < 8; i++) {
        int l = lane + 32 * i;
        float wv = wp[l];
        float4 p = *(float4*)(Ps + l * 4);
        a0 = fmaf(wv, p.x, a0); a1 = fmaf(wv, p.y, a1);
        a2 = fmaf(wv, p.z, a2); a3 = fmaf(wv, p.w, a3);
    }
    for (int o = 16; o; o >>= 1) {
        a0 += __shfl_xor_sync(~0u, a0, o); a1 += __shfl_xor_sync(~0u, a1, o);
        a2 += __shfl_xor_sync(~0u, a2, o); a3 += __shfl_xor_sync(~0u, a3, o);
    }
    if (lane < 4) {
        float v = (lane == 0) ? a0 : (lane == 1) ? a1 : (lane == 2) ? a2 : a3;
        v += blt[t] * g_S[lane] + blg[lane] + g_hid4[((size_t)b * TT + t) * 4 + lane];
        loc_out[((size_t)b * TT + t) * 4 + lane] = sigm(v);
    }
}

extern "C" void kernel_launch(void* const* d_in, const int* in_sizes, int n_in,
                              void* d_out, int out_size)
{
    const float* fea     = (const float*)d_in[0];
    const float* W_i2h   = (const float*)d_in[1];
    const float* W_h2h   = (const float*)d_in[2];
    const float* b_h2h   = (const float*)d_in[3];
    const float* w_score = (const float*)d_in[4];
    const float* W_ih    = (const float*)d_in[5];
    const float* W_hh    = (const float*)d_in[6];
    const float* b_ih    = (const float*)d_in[7];
    const float* b_hh    = (const float*)d_in[8];
    const float* W_gen   = (const float*)d_in[9];
    const float* b_gen   = (const float*)d_in[10];
    const float* Wlt     = (const float*)d_in[11];
    const float* blt     = (const float*)d_in[12];
    const float* W_lg    = (const float*)d_in[13];
    const float* blg     = (const float*)d_in[14];

    float* out = (float*)d_out;
    float* probs = out;
    float* loc   = out + (size_t)BN * TT * 30;

    static int cfg_done = 0;
    if (!cfg_done) {
        cudaFuncSetAttribute(k2_persist, cudaFuncAttributeMaxDynamicSharedMemorySize, SM_FL * 4);
        cfg_done = 1;
    }

    kreset<<<1, 128>>>();
    k0_prep<<<256, 256>>>(W_i2h, W_h2h, W_lg, W_ih);
    kP<<<dim3(32, 128), 256>>>(fea, W_lg);
    k1_gemm<<<dim3(2, 256), 256>>>(fea);
    k2_persist<<<128, 1024, SM_FL * 4>>>(fea, b_h2h, w_score, W_ih, W_hh,
                                         b_ih, b_hh, W_gen, b_gen, W_lg, probs);
    k3_loc<<<dim3(63, 128), 256>>>(Wlt, blt, blg, loc);
}